// round 8
// baseline (speedup 1.0000x reference)
#include <cuda_runtime.h>
#include <cuda_bf16.h>
#include <mma.h>
#include <cstdint>

using namespace nvcuda;

#define BSZ 128
#define TN  512
#define UN  1024
#define MROWS (TN * BSZ)   // 65536

// ---------------- scratch (static device globals) ----------------
__device__ __nv_bfloat16 g_Xhi[(size_t)MROWS * UN];
__device__ __nv_bfloat16 g_Xlo[(size_t)MROWS * UN];
__device__ __nv_bfloat16 g_Ehi[(size_t)MROWS * UN];
__device__ __nv_bfloat16 g_Elo[(size_t)MROWS * UN];
__device__ float         g_ZK [(size_t)MROWS * 4 * UN];   // permuted cols p=u*4+g
__device__ float         g_C  [(size_t)BSZ * UN];
__device__ __nv_bfloat16 g_Hhi[(size_t)(TN + 1) * BSZ * UN];
__device__ __nv_bfloat16 g_Hlo[(size_t)(TN + 1) * BSZ * UN];
__device__ __nv_bfloat16 g_Wemb_hi[(size_t)UN * UN];
__device__ __nv_bfloat16 g_Wemb_lo[(size_t)UN * UN];
__device__ __nv_bfloat16 g_Wout_hi[(size_t)UN * UN];
__device__ __nv_bfloat16 g_Wout_lo[(size_t)UN * UN];
__device__ __nv_bfloat16 g_Wk_hi[(size_t)UN * 4 * UN];    // permuted cols
__device__ __nv_bfloat16 g_Wk_lo[(size_t)UN * 4 * UN];
__device__ __nv_bfloat16 g_Wr_hi[(size_t)UN * 4 * UN];    // permuted cols
__device__ __nv_bfloat16 g_Wr_lo[(size_t)UN * 4 * UN];

struct __align__(8) BF4 { __nv_bfloat16 v[4]; };

__device__ __forceinline__ void bsplit(float v, __nv_bfloat16& h, __nv_bfloat16& l) {
    h = __float2bfloat16(v);
    l = __float2bfloat16(v - __bfloat162float(h));
}

// ---------------- merged prep kernel ----------------
// segments (blockIdx.x), 256 thr, 4 elems/thread in X/W segments:
// [0, 65536)           split_X      (65536*256*4 = 67.1M elems = MROWS*UN)
// [65536, 66048)       init_state   (512*256 = 131072 = BSZ*UN)
// [66048, 67072)       W_emb split  (1024*256*4 = 1M)
// [67072, 68096)       W_out split
// [68096, 72192)       W_k split+perm (4096*256*4 = 4M)
// [72192, 76288)       W_r split+perm
#define PREP_X0    0
#define PREP_ST0   65536
#define PREP_WE0   66048
#define PREP_WO0   67072
#define PREP_WK0   68096
#define PREP_WR0   72192
#define PREP_BLOCKS 76288

__global__ __launch_bounds__(256) void prep_all(
    const float* __restrict__ X, const float* __restrict__ h0, const float* __restrict__ c0,
    const float* __restrict__ W_emb, const float* __restrict__ W_out,
    const float* __restrict__ W_k, const float* __restrict__ W_r)
{
    const int b = blockIdx.x, tid = threadIdx.x;
    if (b < PREP_ST0) {                    // split_X: 4 elems/thread
        size_t i = (size_t)b * 256 + tid;
        size_t e = i * 4;
        size_t r = e >> 10;
        int k = (int)(e & 1023);
        int bb = (int)(r & 127), t = (int)(r >> 7);
        float4 v = *(const float4*)(X + ((size_t)bb * 513 + (size_t)t) * 1024 + k);
        BF4 h, l;
        bsplit(v.x, h.v[0], l.v[0]); bsplit(v.y, h.v[1], l.v[1]);
        bsplit(v.z, h.v[2], l.v[2]); bsplit(v.w, h.v[3], l.v[3]);
        *(BF4*)(g_Xhi + e) = h;
        *(BF4*)(g_Xlo + e) = l;
    } else if (b < PREP_WE0) {             // init_state
        int i = (b - PREP_ST0) * 256 + tid;
        g_C[i] = c0[i];
        __nv_bfloat16 h, l; bsplit(h0[i], h, l);
        g_Hhi[i] = h; g_Hlo[i] = l;
    } else if (b < PREP_WK0) {             // W_emb / W_out (no perm), 4 elems/thread
        int isout = (b >= PREP_WO0);
        const float* W = isout ? W_out : W_emb;
        __nv_bfloat16* hi = isout ? g_Wout_hi : g_Wemb_hi;
        __nv_bfloat16* lo = isout ? g_Wout_lo : g_Wemb_lo;
        size_t q = (size_t)(b - (isout ? PREP_WO0 : PREP_WE0)) * 256 + tid;
        size_t e = q * 4;
        float4 v = *(const float4*)(W + e);
        BF4 h, l;
        bsplit(v.x, h.v[0], l.v[0]); bsplit(v.y, h.v[1], l.v[1]);
        bsplit(v.z, h.v[2], l.v[2]); bsplit(v.w, h.v[3], l.v[3]);
        *(BF4*)(hi + e) = h;
        *(BF4*)(lo + e) = l;
    } else {                               // W_k / W_r permuted, 4 dest cols/thread
        int isr = (b >= PREP_WR0);
        const float* W = isr ? W_r : W_k;
        __nv_bfloat16* hi = isr ? g_Wr_hi : g_Wk_hi;
        __nv_bfloat16* lo = isr ? g_Wr_lo : g_Wk_lo;
        size_t q = (size_t)(b - (isr ? PREP_WR0 : PREP_WK0)) * 256 + tid;
        int row = (int)(q >> 10);
        int qc = (int)(q & 1023);          // dest cols 4qc..4qc+3 = unit qc, gates 0..3
        const float* src = W + (size_t)row * 4096 + qc;
        BF4 h, l;
        bsplit(src[0],    h.v[0], l.v[0]);
        bsplit(src[1024], h.v[1], l.v[1]);
        bsplit(src[2048], h.v[2], l.v[2]);
        bsplit(src[3072], h.v[3], l.v[3]);
        size_t e = (size_t)row * 4096 + (size_t)qc * 4;
        *(BF4*)(hi + e) = h;
        *(BF4*)(lo + e) = l;
    }
}

// ---------------- big bf16-split wmma GEMM (unchanged — near legacy-path peak) ----------------
__global__ __launch_bounds__(256) void wgemm(
    const __nv_bfloat16* __restrict__ Ahi, const __nv_bfloat16* __restrict__ Alo,
    const __nv_bfloat16* __restrict__ Bhi, const __nv_bfloat16* __restrict__ Blo,
    const float* __restrict__ bias, float* __restrict__ D,
    __nv_bfloat16* __restrict__ Dhi, __nv_bfloat16* __restrict__ Dlo,
    int N, int mode)
{
    __shared__ __nv_bfloat16 sAhi[128][40], sAlo[128][40];
    __shared__ __nv_bfloat16 sBhi[32][136], sBlo[32][136];
    __shared__ float sMulti[2048];

    const int tid = threadIdx.x;
    const int n0 = blockIdx.x * 128, m0 = blockIdx.y * 128;
    const int wid = tid >> 5, lane = tid & 31;
    const int wm = wid & 3, wn = wid >> 2;

    float (*sbias)[128] = (float (*)[128])sMulti;
    for (int i = tid; i < 2048; i += 256) {
        int col = i & 127;
        int p = n0 + col;
        float bv = (mode == 1) ? bias[(p & 3) * 1024 + (p >> 2)] : bias[p];
        sbias[i >> 7][col] = bv;
    }
    __syncthreads();

    wmma::fragment<wmma::accumulator, 16, 16, 16, float> acc[2][4];
#pragma unroll
    for (int i = 0; i < 2; i++)
#pragma unroll
        for (int j = 0; j < 4; j++)
            wmma::load_matrix_sync(acc[i][j], &sbias[0][wn * 64 + j * 16], 128, wmma::mem_row_major);
    __syncthreads();

    const int ar0 = tid >> 2,          as_ = (tid & 3) * 8;
    const int ar1 = (tid + 256) >> 2;
    const int br0 = tid >> 4,          bs_ = (tid & 15) * 8;
    const int br1 = (tid + 256) >> 4;

    for (int k0 = 0; k0 < 1024; k0 += 32) {
        int4 a0h = *(const int4*)(Ahi + (size_t)(m0 + ar0) * 1024 + k0 + as_);
        int4 a1h = *(const int4*)(Ahi + (size_t)(m0 + ar1) * 1024 + k0 + as_);
        int4 a0l = *(const int4*)(Alo + (size_t)(m0 + ar0) * 1024 + k0 + as_);
        int4 a1l = *(const int4*)(Alo + (size_t)(m0 + ar1) * 1024 + k0 + as_);
        int4 b0h = *(const int4*)(Bhi + (size_t)(k0 + br0) * N + n0 + bs_);
        int4 b1h = *(const int4*)(Bhi + (size_t)(k0 + br1) * N + n0 + bs_);
        int4 b0l = *(const int4*)(Blo + (size_t)(k0 + br0) * N + n0 + bs_);
        int4 b1l = *(const int4*)(Blo + (size_t)(k0 + br1) * N + n0 + bs_);
        __syncthreads();
        *(int4*)&sAhi[ar0][as_] = a0h; *(int4*)&sAhi[ar1][as_] = a1h;
        *(int4*)&sAlo[ar0][as_] = a0l; *(int4*)&sAlo[ar1][as_] = a1l;
        *(int4*)&sBhi[br0][bs_] = b0h; *(int4*)&sBhi[br1][bs_] = b1h;
        *(int4*)&sBlo[br0][bs_] = b0l; *(int4*)&sBlo[br1][bs_] = b1l;
        __syncthreads();

#pragma unroll
        for (int kk = 0; kk < 32; kk += 16) {
            wmma::fragment<wmma::matrix_a, 16, 16, 16, __nv_bfloat16, wmma::row_major> ah[2], al[2];
            wmma::fragment<wmma::matrix_b, 16, 16, 16, __nv_bfloat16, wmma::row_major> bh[4], bl[4];
#pragma unroll
            for (int i = 0; i < 2; i++) {
                wmma::load_matrix_sync(ah[i], &sAhi[wm * 32 + i * 16][kk], 40);
                wmma::load_matrix_sync(al[i], &sAlo[wm * 32 + i * 16][kk], 40);
            }
#pragma unroll
            for (int j = 0; j < 4; j++) {
                wmma::load_matrix_sync(bh[j], &sBhi[kk][wn * 64 + j * 16], 136);
                wmma::load_matrix_sync(bl[j], &sBlo[kk][wn * 64 + j * 16], 136);
            }
#pragma unroll
            for (int i = 0; i < 2; i++)
#pragma unroll
                for (int j = 0; j < 4; j++) {
                    wmma::mma_sync(acc[i][j], ah[i], bh[j], acc[i][j]);
                    wmma::mma_sync(acc[i][j], ah[i], bl[j], acc[i][j]);
                    wmma::mma_sync(acc[i][j], al[i], bh[j], acc[i][j]);
                }
        }
    }

    if (mode == 0) {
        float (*stage)[16] = (float (*)[16])(sMulti + wid * 256);
        __syncthreads();
#pragma unroll
        for (int i = 0; i < 2; i++)
#pragma unroll
            for (int j = 0; j < 4; j++) {
                for (int e = 0; e < acc[i][j].num_elements; e++)
                    acc[i][j].x[e] = fmaxf(acc[i][j].x[e], 0.f);
                wmma::store_matrix_sync(&stage[0][0], acc[i][j], 16, wmma::mem_row_major);
                __syncwarp();
                int r = lane & 15, c8 = (lane >> 4) * 8;
                size_t row = (size_t)(m0 + wm * 32 + i * 16 + r);
                size_t off = row * 1024 + (n0 + wn * 64 + j * 16 + c8);
                BF4 h0v, l0v, h1v, l1v;
#pragma unroll
                for (int e = 0; e < 4; e++) bsplit(stage[r][c8 + e],     h0v.v[e], l0v.v[e]);
#pragma unroll
                for (int e = 0; e < 4; e++) bsplit(stage[r][c8 + 4 + e], h1v.v[e], l1v.v[e]);
                *(BF4*)(Dhi + off)     = h0v;
                *(BF4*)(Dlo + off)     = l0v;
                *(BF4*)(Dhi + off + 4) = h1v;
                *(BF4*)(Dlo + off + 4) = l1v;
                __syncwarp();
            }
        return;
    }

#pragma unroll
    for (int i = 0; i < 2; i++)
#pragma unroll
        for (int j = 0; j < 4; j++) {
            int col = n0 + wn * 64 + j * 16;
            if (mode == 2) {
                int t = m0 >> 7;
                int b = wm * 32 + i * 16;
                float* p = D + (size_t)t * 1024 + (size_t)b * ((size_t)TN * 1024) + col;
                wmma::store_matrix_sync(p, acc[i][j], (unsigned)(TN * 1024), wmma::mem_row_major);
            } else {
                int row = m0 + wm * 32 + i * 16;
                wmma::store_matrix_sync(D + (size_t)row * N + col, acc[i][j], N, wmma::mem_row_major);
            }
        }
}

// ---------------- recurrent step kernel v3: 6 independent accumulators ----------------
#define STP_ABUF 20480
#define STP_BOFF 61440
#define STP_BBUF 5120
#define STP_TOTAL (STP_BOFF + 3 * STP_BBUF)   // 76800

__device__ __forceinline__ void cp16(uint32_t dst, const void* src) {
    asm volatile("cp.async.cg.shared.global [%0], [%1], 16;" :: "r"(dst), "l"(src));
}
__device__ __forceinline__ void cp_commit() { asm volatile("cp.async.commit_group;"); }
template<int N> __device__ __forceinline__ void cp_wait() {
    asm volatile("cp.async.wait_group %0;" :: "n"(N));
}

__global__ __launch_bounds__(256, 1) void lstm_step3(
    const __nv_bfloat16* __restrict__ Wh_g, const __nv_bfloat16* __restrict__ Wl_g, int t)
{
    extern __shared__ char sm[];
    const uint32_t smb = (uint32_t)__cvta_generic_to_shared(sm);
    const int tid = threadIdx.x, wid = tid >> 5;
    const int bx = blockIdx.x;
    const int n0g = bx * 32;
    const int wm = wid >> 1, wn = wid & 1;

    const __nv_bfloat16* __restrict__ Hhi = g_Hhi + (size_t)t * (BSZ * UN);
    const __nv_bfloat16* __restrict__ Hlo = g_Hlo + (size_t)t * (BSZ * UN);

    const int arow = tid >> 1, aseg = (tid & 1) * 16;
    const int brow = (tid & 127) >> 2, bseg = (tid & 3) * 8;
    const int bislo = tid >> 7;

    auto issue = [&](int chunk) {
        int buf = chunk % 3;
        uint32_t aB = smb + buf * STP_ABUF;
        uint32_t bB = smb + STP_BOFF + buf * STP_BBUF;
        const __nv_bfloat16* sh = Hhi + (size_t)arow * 1024 + chunk * 32 + aseg;
        const __nv_bfloat16* sl = Hlo + (size_t)arow * 1024 + chunk * 32 + aseg;
        uint32_t ad = aB + (uint32_t)(arow * 40 + aseg) * 2;
        cp16(ad,          sh);
        cp16(ad + 16,     sh + 8);
        cp16(ad + 10240,      sl);
        cp16(ad + 10240 + 16, sl + 8);
        const __nv_bfloat16* wsrc = (bislo ? Wl_g : Wh_g) +
            (size_t)(chunk * 32 + brow) * 4096 + n0g + bseg;
        cp16(bB + bislo * 2560 + (uint32_t)(brow * 40 + bseg) * 2, wsrc);
        cp_commit();
    };

    // 6 independent accumulators: [i-tile][product] with product in {hh, hl, lh}
    wmma::fragment<wmma::accumulator, 16, 16, 16, float> acc[2][3];
#pragma unroll
    for (int i = 0; i < 2; i++)
#pragma unroll
        for (int p = 0; p < 3; p++)
            wmma::fill_fragment(acc[i][p], 0.f);

    issue(0);
    issue(1);

    for (int c = 0; c < 32; c++) {
        if (c < 31) cp_wait<1>(); else cp_wait<0>();
        __syncthreads();
        if (c + 2 < 32) issue(c + 2);

        int buf = c % 3;
        __nv_bfloat16 (*Ah)[40] = (__nv_bfloat16 (*)[40])(sm + buf * STP_ABUF);
        __nv_bfloat16 (*Al)[40] = (__nv_bfloat16 (*)[40])(sm + buf * STP_ABUF + 10240);
        __nv_bfloat16 (*Bh)[40] = (__nv_bfloat16 (*)[40])(sm + STP_BOFF + buf * STP_BBUF);
        __nv_bfloat16 (*Bl)[40] = (__nv_bfloat16 (*)[40])(sm + STP_BOFF + buf * STP_BBUF + 2560);

#pragma unroll
        for (int s = 0; s < 2; s++) {
            int kk = s * 16;
            wmma::fragment<wmma::matrix_a, 16, 16, 16, __nv_bfloat16, wmma::row_major> ah0, ah1, al0, al1;
            wmma::fragment<wmma::matrix_b, 16, 16, 16, __nv_bfloat16, wmma::row_major> bh, bl;
            wmma::load_matrix_sync(bh, &Bh[kk][wn * 16], 40);
            wmma::load_matrix_sync(bl, &Bl[kk][wn * 16], 40);
            wmma::load_matrix_sync(ah0, &Ah[wm * 32][kk], 40);
            wmma::load_matrix_sync(ah1, &Ah[wm * 32 + 16][kk], 40);
            wmma::load_matrix_sync(al0, &Al[wm * 32][kk], 40);
            wmma::load_matrix_sync(al1, &Al[wm * 32 + 16][kk], 40);
            // 6 independent accumulator chains — no RAW stalls on the tensor pipe
            wmma::mma_sync(acc[0][0], ah0, bh, acc[0][0]);
            wmma::mma_sync(acc[1][0], ah1, bh, acc[1][0]);
            wmma::mma_sync(acc[0][1], ah0, bl, acc[0][1]);
            wmma::mma_sync(acc[1][1], ah1, bl, acc[1][1]);
            wmma::mma_sync(acc[0][2], al0, bh, acc[0][2]);
            wmma::mma_sync(acc[1][2], al1, bh, acc[1][2]);
        }
    }

    // combine products and stage z in smem
    __syncthreads();
    float (*z)[36] = (float (*)[36])sm;
#pragma unroll
    for (int i = 0; i < 2; i++) {
#pragma unroll
        for (int e = 0; e < acc[0][0].num_elements; e++)
            acc[i][0].x[e] += acc[i][1].x[e] + acc[i][2].x[e];
        wmma::store_matrix_sync(&z[wm * 32 + i * 16][wn * 16], acc[i][0], 36, wmma::mem_row_major);
    }
    __syncthreads();

    // gate epilogue: thread -> row m = tid&127, half = tid>>7 -> 4 units (16 perm cols)
    const int m = tid & 127;
    const int half = tid >> 7;
    const int pc = half * 16;
    const float* __restrict__ zk = g_ZK + ((size_t)t * BSZ + m) * 4096 + n0g + pc;
    float zkf[16];
#pragma unroll
    for (int q = 0; q < 4; q++) {
        float4 v = *(const float4*)(zk + q * 4);
        zkf[q * 4 + 0] = v.x; zkf[q * 4 + 1] = v.y;
        zkf[q * 4 + 2] = v.z; zkf[q * 4 + 3] = v.w;
    }
    float* __restrict__ cptr = g_C + (size_t)m * UN + bx * 8 + half * 4;
    float4 cv4 = *(const float4*)cptr;
    float cv[4] = {cv4.x, cv4.y, cv4.z, cv4.w};
    BF4 hh, hl;
#pragma unroll
    for (int e = 0; e < 4; e++) {
        float zi = z[m][pc + e * 4 + 0] + zkf[e * 4 + 0];
        float zf = z[m][pc + e * 4 + 1] + zkf[e * 4 + 1];
        float zg = z[m][pc + e * 4 + 2] + zkf[e * 4 + 2];
        float zo = z[m][pc + e * 4 + 3] + zkf[e * 4 + 3];
        float si = 1.f / (1.f + __expf(-zi));
        float sf = 1.f / (1.f + __expf(-zf));
        float so = 1.f / (1.f + __expf(-zo));
        float cn = sf * cv[e] + si * tanhf(zg);
        float hn = so * tanhf(cn);
        cv[e] = cn;
        bsplit(hn, hh.v[e], hl.v[e]);
    }
    *(float4*)cptr = make_float4(cv[0], cv[1], cv[2], cv[3]);
    size_t ho = (size_t)(t + 1) * (BSZ * UN) + (size_t)m * UN + bx * 8 + half * 4;
    *(BF4*)(g_Hhi + ho) = hh;
    *(BF4*)(g_Hlo + ho) = hl;
}

// ---------------- host ----------------
extern "C" void kernel_launch(void* const* d_in, const int* in_sizes, int n_in,
                              void* d_out, int out_size)
{
    const float* h0    = (const float*)d_in[0];
    const float* c0    = (const float*)d_in[1];
    const float* X     = (const float*)d_in[2];
    const float* W_emb = (const float*)d_in[3];
    const float* b_emb = (const float*)d_in[4];
    const float* W_k   = (const float*)d_in[5];
    const float* W_r   = (const float*)d_in[6];
    const float* b_r   = (const float*)d_in[7];
    const float* W_out = (const float*)d_in[8];
    const float* b_out = (const float*)d_in[9];
    (void)in_sizes; (void)n_in; (void)out_size;

    __nv_bfloat16 *pXhi, *pXlo, *pEhi, *pElo, *pHhi, *pHlo;
    __nv_bfloat16 *pWembh, *pWembl, *pWouth, *pWoutl, *pWkh, *pWkl, *pWrh, *pWrl;
    float *pZK;
    cudaGetSymbolAddress((void**)&pXhi, g_Xhi);
    cudaGetSymbolAddress((void**)&pXlo, g_Xlo);
    cudaGetSymbolAddress((void**)&pEhi, g_Ehi);
    cudaGetSymbolAddress((void**)&pElo, g_Elo);
    cudaGetSymbolAddress((void**)&pHhi, g_Hhi);
    cudaGetSymbolAddress((void**)&pHlo, g_Hlo);
    cudaGetSymbolAddress((void**)&pWembh, g_Wemb_hi);
    cudaGetSymbolAddress((void**)&pWembl, g_Wemb_lo);
    cudaGetSymbolAddress((void**)&pWouth, g_Wout_hi);
    cudaGetSymbolAddress((void**)&pWoutl, g_Wout_lo);
    cudaGetSymbolAddress((void**)&pWkh, g_Wk_hi);
    cudaGetSymbolAddress((void**)&pWkl, g_Wk_lo);
    cudaGetSymbolAddress((void**)&pWrh, g_Wr_hi);
    cudaGetSymbolAddress((void**)&pWrl, g_Wr_lo);
    cudaGetSymbolAddress((void**)&pZK, g_ZK);

    cudaFuncSetAttribute(lstm_step3, cudaFuncAttributeMaxDynamicSharedMemorySize, STP_TOTAL);

    // 1. merged prep
    prep_all<<<PREP_BLOCKS, 256>>>(X, h0, c0, W_emb, W_out, W_k, W_r);

    // 2. E = relu(X @ W_emb + b_emb), bf16 split written directly
    {
        dim3 grid(1024 / 128, MROWS / 128);
        wgemm<<<grid, 256>>>(pXhi, pXlo, pWembh, pWembl, b_emb,
                             nullptr, pEhi, pElo, 1024, 0);
    }
    // 3. ZK = E @ W_k + b_r
    {
        dim3 grid(4096 / 128, MROWS / 128);
        wgemm<<<grid, 256>>>(pEhi, pElo, pWkh, pWkl, b_r,
                             pZK, nullptr, nullptr, 4096, 1);
    }

    // 4. recurrence: 512 per-step launches
    for (int t = 0; t < TN; t++)
        lstm_step3<<<128, 256, STP_TOTAL>>>(pWrh, pWrl, t);

    // 5. OUT = H @ W_out + b_out, scattered to [b][t][:]
    {
        dim3 grid(1024 / 128, MROWS / 128);
        wgemm<<<grid, 256>>>(pHhi + (size_t)BSZ * UN, pHlo + (size_t)BSZ * UN,
                             pWouth, pWoutl, b_out,
                             (float*)d_out, nullptr, nullptr, 1024, 2);
    }
}

// round 9
// speedup vs baseline: 1.0010x; 1.0010x over previous
#include <cuda_runtime.h>
#include <cuda_bf16.h>
#include <mma.h>
#include <cstdint>

using namespace nvcuda;

#define BSZ 128
#define TN  512
#define UN  1024
#define MROWS (TN * BSZ)   // 65536

// ---------------- scratch (static device globals) ----------------
__device__ __nv_bfloat16 g_Xhi[(size_t)MROWS * UN];
__device__ __nv_bfloat16 g_Xlo[(size_t)MROWS * UN];
__device__ __nv_bfloat16 g_Ehi[(size_t)MROWS * UN];
__device__ __nv_bfloat16 g_Elo[(size_t)MROWS * UN];
__device__ float         g_ZK [(size_t)MROWS * 4 * UN];   // permuted cols p=u*4+g
__device__ float         g_C  [(size_t)BSZ * UN];
__device__ __nv_bfloat16 g_Hhi[(size_t)(TN + 1) * BSZ * UN];
__device__ __nv_bfloat16 g_Hlo[(size_t)(TN + 1) * BSZ * UN];
__device__ __nv_bfloat16 g_Wemb_hi[(size_t)UN * UN];
__device__ __nv_bfloat16 g_Wemb_lo[(size_t)UN * UN];
__device__ __nv_bfloat16 g_Wout_hi[(size_t)UN * UN];
__device__ __nv_bfloat16 g_Wout_lo[(size_t)UN * UN];
__device__ __nv_bfloat16 g_Wk_hi[(size_t)UN * 4 * UN];    // permuted cols
__device__ __nv_bfloat16 g_Wk_lo[(size_t)UN * 4 * UN];
__device__ __nv_bfloat16 g_Wr_hi[(size_t)UN * 4 * UN];    // permuted cols
__device__ __nv_bfloat16 g_Wr_lo[(size_t)UN * 4 * UN];

struct __align__(8) BF4 { __nv_bfloat16 v[4]; };

__device__ __forceinline__ void bsplit(float v, __nv_bfloat16& h, __nv_bfloat16& l) {
    h = __float2bfloat16(v);
    l = __float2bfloat16(v - __bfloat162float(h));
}

// ---------------- merged prep kernel ----------------
// [0,65536) split_X | [65536,66048) init_state | [66048,67072) W_emb |
// [67072,68096) W_out | [68096,72192) W_k perm | [72192,76288) W_r perm
#define PREP_ST0   65536
#define PREP_WE0   66048
#define PREP_WO0   67072
#define PREP_WK0   68096
#define PREP_WR0   72192
#define PREP_BLOCKS 76288

__global__ __launch_bounds__(256) void prep_all(
    const float* __restrict__ X, const float* __restrict__ h0, const float* __restrict__ c0,
    const float* __restrict__ W_emb, const float* __restrict__ W_out,
    const float* __restrict__ W_k, const float* __restrict__ W_r)
{
    const int b = blockIdx.x, tid = threadIdx.x;
    if (b < PREP_ST0) {                    // split_X: 4 elems/thread
        size_t i = (size_t)b * 256 + tid;
        size_t e = i * 4;
        size_t r = e >> 10;
        int k = (int)(e & 1023);
        int bb = (int)(r & 127), t = (int)(r >> 7);
        float4 v = *(const float4*)(X + ((size_t)bb * 513 + (size_t)t) * 1024 + k);
        BF4 h, l;
        bsplit(v.x, h.v[0], l.v[0]); bsplit(v.y, h.v[1], l.v[1]);
        bsplit(v.z, h.v[2], l.v[2]); bsplit(v.w, h.v[3], l.v[3]);
        *(BF4*)(g_Xhi + e) = h;
        *(BF4*)(g_Xlo + e) = l;
    } else if (b < PREP_WE0) {             // init_state
        int i = (b - PREP_ST0) * 256 + tid;
        g_C[i] = c0[i];
        __nv_bfloat16 h, l; bsplit(h0[i], h, l);
        g_Hhi[i] = h; g_Hlo[i] = l;
    } else if (b < PREP_WK0) {             // W_emb / W_out (no perm)
        int isout = (b >= PREP_WO0);
        const float* W = isout ? W_out : W_emb;
        __nv_bfloat16* hi = isout ? g_Wout_hi : g_Wemb_hi;
        __nv_bfloat16* lo = isout ? g_Wout_lo : g_Wemb_lo;
        size_t q = (size_t)(b - (isout ? PREP_WO0 : PREP_WE0)) * 256 + tid;
        size_t e = q * 4;
        float4 v = *(const float4*)(W + e);
        BF4 h, l;
        bsplit(v.x, h.v[0], l.v[0]); bsplit(v.y, h.v[1], l.v[1]);
        bsplit(v.z, h.v[2], l.v[2]); bsplit(v.w, h.v[3], l.v[3]);
        *(BF4*)(hi + e) = h;
        *(BF4*)(lo + e) = l;
    } else {                               // W_k / W_r permuted
        int isr = (b >= PREP_WR0);
        const float* W = isr ? W_r : W_k;
        __nv_bfloat16* hi = isr ? g_Wr_hi : g_Wk_hi;
        __nv_bfloat16* lo = isr ? g_Wr_lo : g_Wk_lo;
        size_t q = (size_t)(b - (isr ? PREP_WR0 : PREP_WK0)) * 256 + tid;
        int row = (int)(q >> 10);
        int qc = (int)(q & 1023);
        const float* src = W + (size_t)row * 4096 + qc;
        BF4 h, l;
        bsplit(src[0],    h.v[0], l.v[0]);
        bsplit(src[1024], h.v[1], l.v[1]);
        bsplit(src[2048], h.v[2], l.v[2]);
        bsplit(src[3072], h.v[3], l.v[3]);
        size_t e = (size_t)row * 4096 + (size_t)qc * 4;
        *(BF4*)(hi + e) = h;
        *(BF4*)(lo + e) = l;
    }
}

// ---------------- big bf16-split wmma GEMM (unchanged) ----------------
__global__ __launch_bounds__(256) void wgemm(
    const __nv_bfloat16* __restrict__ Ahi, const __nv_bfloat16* __restrict__ Alo,
    const __nv_bfloat16* __restrict__ Bhi, const __nv_bfloat16* __restrict__ Blo,
    const float* __restrict__ bias, float* __restrict__ D,
    __nv_bfloat16* __restrict__ Dhi, __nv_bfloat16* __restrict__ Dlo,
    int N, int mode)
{
    __shared__ __nv_bfloat16 sAhi[128][40], sAlo[128][40];
    __shared__ __nv_bfloat16 sBhi[32][136], sBlo[32][136];
    __shared__ float sMulti[2048];

    const int tid = threadIdx.x;
    const int n0 = blockIdx.x * 128, m0 = blockIdx.y * 128;
    const int wid = tid >> 5, lane = tid & 31;
    const int wm = wid & 3, wn = wid >> 2;

    float (*sbias)[128] = (float (*)[128])sMulti;
    for (int i = tid; i < 2048; i += 256) {
        int col = i & 127;
        int p = n0 + col;
        float bv = (mode == 1) ? bias[(p & 3) * 1024 + (p >> 2)] : bias[p];
        sbias[i >> 7][col] = bv;
    }
    __syncthreads();

    wmma::fragment<wmma::accumulator, 16, 16, 16, float> acc[2][4];
#pragma unroll
    for (int i = 0; i < 2; i++)
#pragma unroll
        for (int j = 0; j < 4; j++)
            wmma::load_matrix_sync(acc[i][j], &sbias[0][wn * 64 + j * 16], 128, wmma::mem_row_major);
    __syncthreads();

    const int ar0 = tid >> 2,          as_ = (tid & 3) * 8;
    const int ar1 = (tid + 256) >> 2;
    const int br0 = tid >> 4,          bs_ = (tid & 15) * 8;
    const int br1 = (tid + 256) >> 4;

    for (int k0 = 0; k0 < 1024; k0 += 32) {
        int4 a0h = *(const int4*)(Ahi + (size_t)(m0 + ar0) * 1024 + k0 + as_);
        int4 a1h = *(const int4*)(Ahi + (size_t)(m0 + ar1) * 1024 + k0 + as_);
        int4 a0l = *(const int4*)(Alo + (size_t)(m0 + ar0) * 1024 + k0 + as_);
        int4 a1l = *(const int4*)(Alo + (size_t)(m0 + ar1) * 1024 + k0 + as_);
        int4 b0h = *(const int4*)(Bhi + (size_t)(k0 + br0) * N + n0 + bs_);
        int4 b1h = *(const int4*)(Bhi + (size_t)(k0 + br1) * N + n0 + bs_);
        int4 b0l = *(const int4*)(Blo + (size_t)(k0 + br0) * N + n0 + bs_);
        int4 b1l = *(const int4*)(Blo + (size_t)(k0 + br1) * N + n0 + bs_);
        __syncthreads();
        *(int4*)&sAhi[ar0][as_] = a0h; *(int4*)&sAhi[ar1][as_] = a1h;
        *(int4*)&sAlo[ar0][as_] = a0l; *(int4*)&sAlo[ar1][as_] = a1l;
        *(int4*)&sBhi[br0][bs_] = b0h; *(int4*)&sBhi[br1][bs_] = b1h;
        *(int4*)&sBlo[br0][bs_] = b0l; *(int4*)&sBlo[br1][bs_] = b1l;
        __syncthreads();

#pragma unroll
        for (int kk = 0; kk < 32; kk += 16) {
            wmma::fragment<wmma::matrix_a, 16, 16, 16, __nv_bfloat16, wmma::row_major> ah[2], al[2];
            wmma::fragment<wmma::matrix_b, 16, 16, 16, __nv_bfloat16, wmma::row_major> bh[4], bl[4];
#pragma unroll
            for (int i = 0; i < 2; i++) {
                wmma::load_matrix_sync(ah[i], &sAhi[wm * 32 + i * 16][kk], 40);
                wmma::load_matrix_sync(al[i], &sAlo[wm * 32 + i * 16][kk], 40);
            }
#pragma unroll
            for (int j = 0; j < 4; j++) {
                wmma::load_matrix_sync(bh[j], &sBhi[kk][wn * 64 + j * 16], 136);
                wmma::load_matrix_sync(bl[j], &sBlo[kk][wn * 64 + j * 16], 136);
            }
#pragma unroll
            for (int i = 0; i < 2; i++)
#pragma unroll
                for (int j = 0; j < 4; j++) {
                    wmma::mma_sync(acc[i][j], ah[i], bh[j], acc[i][j]);
                    wmma::mma_sync(acc[i][j], ah[i], bl[j], acc[i][j]);
                    wmma::mma_sync(acc[i][j], al[i], bh[j], acc[i][j]);
                }
        }
    }

    if (mode == 0) {
        float (*stage)[16] = (float (*)[16])(sMulti + wid * 256);
        __syncthreads();
#pragma unroll
        for (int i = 0; i < 2; i++)
#pragma unroll
            for (int j = 0; j < 4; j++) {
                for (int e = 0; e < acc[i][j].num_elements; e++)
                    acc[i][j].x[e] = fmaxf(acc[i][j].x[e], 0.f);
                wmma::store_matrix_sync(&stage[0][0], acc[i][j], 16, wmma::mem_row_major);
                __syncwarp();
                int r = lane & 15, c8 = (lane >> 4) * 8;
                size_t row = (size_t)(m0 + wm * 32 + i * 16 + r);
                size_t off = row * 1024 + (n0 + wn * 64 + j * 16 + c8);
                BF4 h0v, l0v, h1v, l1v;
#pragma unroll
                for (int e = 0; e < 4; e++) bsplit(stage[r][c8 + e],     h0v.v[e], l0v.v[e]);
#pragma unroll
                for (int e = 0; e < 4; e++) bsplit(stage[r][c8 + 4 + e], h1v.v[e], l1v.v[e]);
                *(BF4*)(Dhi + off)     = h0v;
                *(BF4*)(Dlo + off)     = l0v;
                *(BF4*)(Dhi + off + 4) = h1v;
                *(BF4*)(Dlo + off + 4) = l1v;
                __syncwarp();
            }
        return;
    }

#pragma unroll
    for (int i = 0; i < 2; i++)
#pragma unroll
        for (int j = 0; j < 4; j++) {
            int col = n0 + wn * 64 + j * 16;
            if (mode == 2) {
                int t = m0 >> 7;
                int b = wm * 32 + i * 16;
                float* p = D + (size_t)t * 1024 + (size_t)b * ((size_t)TN * 1024) + col;
                wmma::store_matrix_sync(p, acc[i][j], (unsigned)(TN * 1024), wmma::mem_row_major);
            } else {
                int row = m0 + wm * 32 + i * 16;
                wmma::store_matrix_sync(D + (size_t)row * N + col, acc[i][j], N, wmma::mem_row_major);
            }
        }
}

// ---------------- recurrent step kernel v4: 512 threads / 16 warps ----------------
// 128 CTAs x 512 thr. Warp (wm=wid>>1, wn=wid&1): M16 x N16 tile, 3 indep acc chains.
// K-chunk 32, 3-stage cp.async, stride-40 conflict-free smem.
#define STP_ABUF 20480
#define STP_BOFF 61440
#define STP_BBUF 5120
#define STP_TOTAL (STP_BOFF + 3 * STP_BBUF)   // 76800

__device__ __forceinline__ void cp16(uint32_t dst, const void* src) {
    asm volatile("cp.async.cg.shared.global [%0], [%1], 16;" :: "r"(dst), "l"(src));
}
__device__ __forceinline__ void cp_commit() { asm volatile("cp.async.commit_group;"); }
template<int N> __device__ __forceinline__ void cp_wait() {
    asm volatile("cp.async.wait_group %0;" :: "n"(N));
}

__global__ __launch_bounds__(512, 1) void lstm_step4(
    const __nv_bfloat16* __restrict__ Wh_g, const __nv_bfloat16* __restrict__ Wl_g, int t)
{
    extern __shared__ char sm[];
    const uint32_t smb = (uint32_t)__cvta_generic_to_shared(sm);
    const int tid = threadIdx.x, wid = tid >> 5;
    const int bx = blockIdx.x;
    const int n0g = bx * 32;
    const int wm = wid >> 1, wn = wid & 1;

    const __nv_bfloat16* __restrict__ Hhi = g_Hhi + (size_t)t * (BSZ * UN);
    const __nv_bfloat16* __restrict__ Hlo = g_Hlo + (size_t)t * (BSZ * UN);

    // cp.async mapping: A = 512 thr x 1 cp16 per split; B = 256 thr x 1 cp16
    const int arow = tid >> 2, aseg = (tid & 3) * 8;
    const int brow = (tid & 127) >> 2, bseg = (tid & 3) * 8;
    const int bislo = (tid >> 7) & 1;
    const bool bactive = (tid < 256);

    auto issue = [&](int chunk) {
        int buf = chunk % 3;
        uint32_t aB = smb + buf * STP_ABUF;
        uint32_t bB = smb + STP_BOFF + buf * STP_BBUF;
        uint32_t ad = aB + (uint32_t)(arow * 40 + aseg) * 2;
        cp16(ad,         Hhi + (size_t)arow * 1024 + chunk * 32 + aseg);
        cp16(ad + 10240, Hlo + (size_t)arow * 1024 + chunk * 32 + aseg);
        if (bactive) {
            const __nv_bfloat16* wsrc = (bislo ? Wl_g : Wh_g) +
                (size_t)(chunk * 32 + brow) * 4096 + n0g + bseg;
            cp16(bB + bislo * 2560 + (uint32_t)(brow * 40 + bseg) * 2, wsrc);
        }
        cp_commit();
    };

    // 3 independent accumulator chains per warp: hh, hl, lh
    wmma::fragment<wmma::accumulator, 16, 16, 16, float> acc0, acc1, acc2;
    wmma::fill_fragment(acc0, 0.f);
    wmma::fill_fragment(acc1, 0.f);
    wmma::fill_fragment(acc2, 0.f);

    issue(0);
    issue(1);

    for (int c = 0; c < 32; c++) {
        if (c < 31) cp_wait<1>(); else cp_wait<0>();
        __syncthreads();
        if (c + 2 < 32) issue(c + 2);

        int buf = c % 3;
        __nv_bfloat16 (*Ah)[40] = (__nv_bfloat16 (*)[40])(sm + buf * STP_ABUF);
        __nv_bfloat16 (*Al)[40] = (__nv_bfloat16 (*)[40])(sm + buf * STP_ABUF + 10240);
        __nv_bfloat16 (*Bh)[40] = (__nv_bfloat16 (*)[40])(sm + STP_BOFF + buf * STP_BBUF);
        __nv_bfloat16 (*Bl)[40] = (__nv_bfloat16 (*)[40])(sm + STP_BOFF + buf * STP_BBUF + 2560);

#pragma unroll
        for (int s = 0; s < 2; s++) {
            int kk = s * 16;
            wmma::fragment<wmma::matrix_a, 16, 16, 16, __nv_bfloat16, wmma::row_major> ah, al;
            wmma::fragment<wmma::matrix_b, 16, 16, 16, __nv_bfloat16, wmma::row_major> bh, bl;
            wmma::load_matrix_sync(bh, &Bh[kk][wn * 16], 40);
            wmma::load_matrix_sync(bl, &Bl[kk][wn * 16], 40);
            wmma::load_matrix_sync(ah, &Ah[wm * 16][kk], 40);
            wmma::load_matrix_sync(al, &Al[wm * 16][kk], 40);
            wmma::mma_sync(acc0, ah, bh, acc0);
            wmma::mma_sync(acc1, ah, bl, acc1);
            wmma::mma_sync(acc2, al, bh, acc2);
        }
    }

    // combine products and stage z in smem (overlay on A buffers)
    __syncthreads();
    float (*z)[36] = (float (*)[36])sm;
#pragma unroll
    for (int e = 0; e < acc0.num_elements; e++)
        acc0.x[e] += acc1.x[e] + acc2.x[e];
    wmma::store_matrix_sync(&z[wm * 16][wn * 16], acc0, 36, wmma::mem_row_major);
    __syncthreads();

    // gate epilogue: thread -> row m = tid&127, grp = tid>>7 (0..3) -> 2 units (8 perm cols)
    const int m = tid & 127;
    const int grp = tid >> 7;
    const int pc = grp * 8;
    const float* __restrict__ zk = g_ZK + ((size_t)t * BSZ + m) * 4096 + n0g + pc;
    float zkf[8];
    {
        float4 v0 = *(const float4*)(zk);
        float4 v1 = *(const float4*)(zk + 4);
        zkf[0] = v0.x; zkf[1] = v0.y; zkf[2] = v0.z; zkf[3] = v0.w;
        zkf[4] = v1.x; zkf[5] = v1.y; zkf[6] = v1.z; zkf[7] = v1.w;
    }
    float* __restrict__ cptr = g_C + (size_t)m * UN + bx * 8 + grp * 2;
    float2 cv2 = *(const float2*)cptr;
    float cv[2] = {cv2.x, cv2.y};
    __nv_bfloat162 hh2, hl2;
#pragma unroll
    for (int e = 0; e < 2; e++) {
        float zi = z[m][pc + e * 4 + 0] + zkf[e * 4 + 0];
        float zf = z[m][pc + e * 4 + 1] + zkf[e * 4 + 1];
        float zg = z[m][pc + e * 4 + 2] + zkf[e * 4 + 2];
        float zo = z[m][pc + e * 4 + 3] + zkf[e * 4 + 3];
        float si = 1.f / (1.f + __expf(-zi));
        float sf = 1.f / (1.f + __expf(-zf));
        float so = 1.f / (1.f + __expf(-zo));
        float cn = sf * cv[e] + si * tanhf(zg);
        float hn = so * tanhf(cn);
        cv[e] = cn;
        __nv_bfloat16 h, l; bsplit(hn, h, l);
        if (e == 0) { hh2.x = h; hl2.x = l; } else { hh2.y = h; hl2.y = l; }
    }
    *(float2*)cptr = make_float2(cv[0], cv[1]);
    size_t ho = (size_t)(t + 1) * (BSZ * UN) + (size_t)m * UN + bx * 8 + grp * 2;
    *(__nv_bfloat162*)(g_Hhi + ho) = hh2;
    *(__nv_bfloat162*)(g_Hlo + ho) = hl2;
}

// ---------------- host ----------------
extern "C" void kernel_launch(void* const* d_in, const int* in_sizes, int n_in,
                              void* d_out, int out_size)
{
    const float* h0    = (const float*)d_in[0];
    const float* c0    = (const float*)d_in[1];
    const float* X     = (const float*)d_in[2];
    const float* W_emb = (const float*)d_in[3];
    const float* b_emb = (const float*)d_in[4];
    const float* W_k   = (const float*)d_in[5];
    const float* W_r   = (const float*)d_in[6];
    const float* b_r   = (const float*)d_in[7];
    const float* W_out = (const float*)d_in[8];
    const float* b_out = (const float*)d_in[9];
    (void)in_sizes; (void)n_in; (void)out_size;

    __nv_bfloat16 *pXhi, *pXlo, *pEhi, *pElo, *pHhi, *pHlo;
    __nv_bfloat16 *pWembh, *pWembl, *pWouth, *pWoutl, *pWkh, *pWkl, *pWrh, *pWrl;
    float *pZK;
    cudaGetSymbolAddress((void**)&pXhi, g_Xhi);
    cudaGetSymbolAddress((void**)&pXlo, g_Xlo);
    cudaGetSymbolAddress((void**)&pEhi, g_Ehi);
    cudaGetSymbolAddress((void**)&pElo, g_Elo);
    cudaGetSymbolAddress((void**)&pHhi, g_Hhi);
    cudaGetSymbolAddress((void**)&pHlo, g_Hlo);
    cudaGetSymbolAddress((void**)&pWembh, g_Wemb_hi);
    cudaGetSymbolAddress((void**)&pWembl, g_Wemb_lo);
    cudaGetSymbolAddress((void**)&pWouth, g_Wout_hi);
    cudaGetSymbolAddress((void**)&pWoutl, g_Wout_lo);
    cudaGetSymbolAddress((void**)&pWkh, g_Wk_hi);
    cudaGetSymbolAddress((void**)&pWkl, g_Wk_lo);
    cudaGetSymbolAddress((void**)&pWrh, g_Wr_hi);
    cudaGetSymbolAddress((void**)&pWrl, g_Wr_lo);
    cudaGetSymbolAddress((void**)&pZK, g_ZK);

    cudaFuncSetAttribute(lstm_step4, cudaFuncAttributeMaxDynamicSharedMemorySize, STP_TOTAL);

    // 1. merged prep
    prep_all<<<PREP_BLOCKS, 256>>>(X, h0, c0, W_emb, W_out, W_k, W_r);

    // 2. E = relu(X @ W_emb + b_emb), bf16 split written directly
    {
        dim3 grid(1024 / 128, MROWS / 128);
        wgemm<<<grid, 256>>>(pXhi, pXlo, pWembh, pWembl, b_emb,
                             nullptr, pEhi, pElo, 1024, 0);
    }
    // 3. ZK = E @ W_k + b_r
    {
        dim3 grid(4096 / 128, MROWS / 128);
        wgemm<<<grid, 256>>>(pEhi, pElo, pWkh, pWkl, b_r,
                             pZK, nullptr, nullptr, 4096, 1);
    }

    // 4. recurrence: 512 per-step launches, 16-warp step kernel
    for (int t = 0; t < TN; t++)
        lstm_step4<<<128, 512, STP_TOTAL>>>(pWrh, pWrl, t);

    // 5. OUT = H @ W_out + b_out, scattered to [b][t][:]
    {
        dim3 grid(1024 / 128, MROWS / 128);
        wgemm<<<grid, 256>>>(pHhi + (size_t)BSZ * UN, pHlo + (size_t)BSZ * UN,
                             pWouth, pWoutl, b_out,
                             (float*)d_out, nullptr, nullptr, 1024, 2);
    }
}

// round 10
// speedup vs baseline: 1.0433x; 1.0422x over previous
#include <cuda_runtime.h>
#include <cuda_bf16.h>
#include <mma.h>
#include <cstdint>

using namespace nvcuda;

#define BSZ 128
#define TN  512
#define UN  1024
#define MROWS (TN * BSZ)   // 65536
#define NCTA 128

// ---------------- scratch (static device globals) ----------------
__device__ __nv_bfloat16 g_Xhi[(size_t)MROWS * UN];
__device__ __nv_bfloat16 g_Xlo[(size_t)MROWS * UN];
__device__ __nv_bfloat16 g_Ehi[(size_t)MROWS * UN];
__device__ __nv_bfloat16 g_Elo[(size_t)MROWS * UN];
__device__ float         g_ZK [(size_t)MROWS * 4 * UN];   // permuted cols p=u*4+g
__device__ float         g_C  [(size_t)BSZ * UN];
__device__ __nv_bfloat16 g_Hhi[(size_t)(TN + 1) * BSZ * UN];
__device__ __nv_bfloat16 g_Hlo[(size_t)(TN + 1) * BSZ * UN];
__device__ __nv_bfloat16 g_Wemb_hi[(size_t)UN * UN];
__device__ __nv_bfloat16 g_Wemb_lo[(size_t)UN * UN];
__device__ __nv_bfloat16 g_Wout_hi[(size_t)UN * UN];
__device__ __nv_bfloat16 g_Wout_lo[(size_t)UN * UN];
__device__ __nv_bfloat16 g_Wk_hi[(size_t)UN * 4 * UN];    // permuted cols
__device__ __nv_bfloat16 g_Wk_lo[(size_t)UN * 4 * UN];
__device__ __nv_bfloat16 g_Wr_hi[(size_t)UN * 4 * UN];    // permuted cols
__device__ __nv_bfloat16 g_Wr_lo[(size_t)UN * 4 * UN];
__device__ int           g_count;

struct __align__(8) BF4 { __nv_bfloat16 v[4]; };

__device__ __forceinline__ void bsplit(float v, __nv_bfloat16& h, __nv_bfloat16& l) {
    h = __float2bfloat16(v);
    l = __float2bfloat16(v - __bfloat162float(h));
}

// ---------------- merged prep kernel ----------------
// [0,65536) split_X | [65536,66048) init_state | [66048,67072) W_emb |
// [67072,68096) W_out | [68096,72192) W_k perm | [72192,76288) W_r perm
#define PREP_ST0   65536
#define PREP_WE0   66048
#define PREP_WO0   67072
#define PREP_WK0   68096
#define PREP_WR0   72192
#define PREP_BLOCKS 76288

__global__ __launch_bounds__(256) void prep_all(
    const float* __restrict__ X, const float* __restrict__ h0, const float* __restrict__ c0,
    const float* __restrict__ W_emb, const float* __restrict__ W_out,
    const float* __restrict__ W_k, const float* __restrict__ W_r)
{
    const int b = blockIdx.x, tid = threadIdx.x;
    if (b < PREP_ST0) {                    // split_X: 4 elems/thread
        size_t i = (size_t)b * 256 + tid;
        size_t e = i * 4;
        size_t r = e >> 10;
        int k = (int)(e & 1023);
        int bb = (int)(r & 127), t = (int)(r >> 7);
        float4 v = *(const float4*)(X + ((size_t)bb * 513 + (size_t)t) * 1024 + k);
        BF4 h, l;
        bsplit(v.x, h.v[0], l.v[0]); bsplit(v.y, h.v[1], l.v[1]);
        bsplit(v.z, h.v[2], l.v[2]); bsplit(v.w, h.v[3], l.v[3]);
        *(BF4*)(g_Xhi + e) = h;
        *(BF4*)(g_Xlo + e) = l;
    } else if (b < PREP_WE0) {             // init_state
        int i = (b - PREP_ST0) * 256 + tid;
        if (b == PREP_ST0 && tid == 0) g_count = 0;
        g_C[i] = c0[i];
        __nv_bfloat16 h, l; bsplit(h0[i], h, l);
        g_Hhi[i] = h; g_Hlo[i] = l;
    } else if (b < PREP_WK0) {             // W_emb / W_out (no perm)
        int isout = (b >= PREP_WO0);
        const float* W = isout ? W_out : W_emb;
        __nv_bfloat16* hi = isout ? g_Wout_hi : g_Wemb_hi;
        __nv_bfloat16* lo = isout ? g_Wout_lo : g_Wemb_lo;
        size_t q = (size_t)(b - (isout ? PREP_WO0 : PREP_WE0)) * 256 + tid;
        size_t e = q * 4;
        float4 v = *(const float4*)(W + e);
        BF4 h, l;
        bsplit(v.x, h.v[0], l.v[0]); bsplit(v.y, h.v[1], l.v[1]);
        bsplit(v.z, h.v[2], l.v[2]); bsplit(v.w, h.v[3], l.v[3]);
        *(BF4*)(hi + e) = h;
        *(BF4*)(lo + e) = l;
    } else {                               // W_k / W_r permuted
        int isr = (b >= PREP_WR0);
        const float* W = isr ? W_r : W_k;
        __nv_bfloat16* hi = isr ? g_Wr_hi : g_Wk_hi;
        __nv_bfloat16* lo = isr ? g_Wr_lo : g_Wk_lo;
        size_t q = (size_t)(b - (isr ? PREP_WR0 : PREP_WK0)) * 256 + tid;
        int row = (int)(q >> 10);
        int qc = (int)(q & 1023);
        const float* src = W + (size_t)row * 4096 + qc;
        BF4 h, l;
        bsplit(src[0],    h.v[0], l.v[0]);
        bsplit(src[1024], h.v[1], l.v[1]);
        bsplit(src[2048], h.v[2], l.v[2]);
        bsplit(src[3072], h.v[3], l.v[3]);
        size_t e = (size_t)row * 4096 + (size_t)qc * 4;
        *(BF4*)(hi + e) = h;
        *(BF4*)(lo + e) = l;
    }
}

// ---------------- big bf16-split wmma GEMM (unchanged) ----------------
__global__ __launch_bounds__(256) void wgemm(
    const __nv_bfloat16* __restrict__ Ahi, const __nv_bfloat16* __restrict__ Alo,
    const __nv_bfloat16* __restrict__ Bhi, const __nv_bfloat16* __restrict__ Blo,
    const float* __restrict__ bias, float* __restrict__ D,
    __nv_bfloat16* __restrict__ Dhi, __nv_bfloat16* __restrict__ Dlo,
    int N, int mode)
{
    __shared__ __nv_bfloat16 sAhi[128][40], sAlo[128][40];
    __shared__ __nv_bfloat16 sBhi[32][136], sBlo[32][136];
    __shared__ float sMulti[2048];

    const int tid = threadIdx.x;
    const int n0 = blockIdx.x * 128, m0 = blockIdx.y * 128;
    const int wid = tid >> 5, lane = tid & 31;
    const int wm = wid & 3, wn = wid >> 2;

    float (*sbias)[128] = (float (*)[128])sMulti;
    for (int i = tid; i < 2048; i += 256) {
        int col = i & 127;
        int p = n0 + col;
        float bv = (mode == 1) ? bias[(p & 3) * 1024 + (p >> 2)] : bias[p];
        sbias[i >> 7][col] = bv;
    }
    __syncthreads();

    wmma::fragment<wmma::accumulator, 16, 16, 16, float> acc[2][4];
#pragma unroll
    for (int i = 0; i < 2; i++)
#pragma unroll
        for (int j = 0; j < 4; j++)
            wmma::load_matrix_sync(acc[i][j], &sbias[0][wn * 64 + j * 16], 128, wmma::mem_row_major);
    __syncthreads();

    const int ar0 = tid >> 2,          as_ = (tid & 3) * 8;
    const int ar1 = (tid + 256) >> 2;
    const int br0 = tid >> 4,          bs_ = (tid & 15) * 8;
    const int br1 = (tid + 256) >> 4;

    for (int k0 = 0; k0 < 1024; k0 += 32) {
        int4 a0h = *(const int4*)(Ahi + (size_t)(m0 + ar0) * 1024 + k0 + as_);
        int4 a1h = *(const int4*)(Ahi + (size_t)(m0 + ar1) * 1024 + k0 + as_);
        int4 a0l = *(const int4*)(Alo + (size_t)(m0 + ar0) * 1024 + k0 + as_);
        int4 a1l = *(const int4*)(Alo + (size_t)(m0 + ar1) * 1024 + k0 + as_);
        int4 b0h = *(const int4*)(Bhi + (size_t)(k0 + br0) * N + n0 + bs_);
        int4 b1h = *(const int4*)(Bhi + (size_t)(k0 + br1) * N + n0 + bs_);
        int4 b0l = *(const int4*)(Blo + (size_t)(k0 + br0) * N + n0 + bs_);
        int4 b1l = *(const int4*)(Blo + (size_t)(k0 + br1) * N + n0 + bs_);
        __syncthreads();
        *(int4*)&sAhi[ar0][as_] = a0h; *(int4*)&sAhi[ar1][as_] = a1h;
        *(int4*)&sAlo[ar0][as_] = a0l; *(int4*)&sAlo[ar1][as_] = a1l;
        *(int4*)&sBhi[br0][bs_] = b0h; *(int4*)&sBhi[br1][bs_] = b1h;
        *(int4*)&sBlo[br0][bs_] = b0l; *(int4*)&sBlo[br1][bs_] = b1l;
        __syncthreads();

#pragma unroll
        for (int kk = 0; kk < 32; kk += 16) {
            wmma::fragment<wmma::matrix_a, 16, 16, 16, __nv_bfloat16, wmma::row_major> ah[2], al[2];
            wmma::fragment<wmma::matrix_b, 16, 16, 16, __nv_bfloat16, wmma::row_major> bh[4], bl[4];
#pragma unroll
            for (int i = 0; i < 2; i++) {
                wmma::load_matrix_sync(ah[i], &sAhi[wm * 32 + i * 16][kk], 40);
                wmma::load_matrix_sync(al[i], &sAlo[wm * 32 + i * 16][kk], 40);
            }
#pragma unroll
            for (int j = 0; j < 4; j++) {
                wmma::load_matrix_sync(bh[j], &sBhi[kk][wn * 64 + j * 16], 136);
                wmma::load_matrix_sync(bl[j], &sBlo[kk][wn * 64 + j * 16], 136);
            }
#pragma unroll
            for (int i = 0; i < 2; i++)
#pragma unroll
                for (int j = 0; j < 4; j++) {
                    wmma::mma_sync(acc[i][j], ah[i], bh[j], acc[i][j]);
                    wmma::mma_sync(acc[i][j], ah[i], bl[j], acc[i][j]);
                    wmma::mma_sync(acc[i][j], al[i], bh[j], acc[i][j]);
                }
        }
    }

    if (mode == 0) {
        float (*stage)[16] = (float (*)[16])(sMulti + wid * 256);
        __syncthreads();
#pragma unroll
        for (int i = 0; i < 2; i++)
#pragma unroll
            for (int j = 0; j < 4; j++) {
                for (int e = 0; e < acc[i][j].num_elements; e++)
                    acc[i][j].x[e] = fmaxf(acc[i][j].x[e], 0.f);
                wmma::store_matrix_sync(&stage[0][0], acc[i][j], 16, wmma::mem_row_major);
                __syncwarp();
                int r = lane & 15, c8 = (lane >> 4) * 8;
                size_t row = (size_t)(m0 + wm * 32 + i * 16 + r);
                size_t off = row * 1024 + (n0 + wn * 64 + j * 16 + c8);
                BF4 h0v, l0v, h1v, l1v;
#pragma unroll
                for (int e = 0; e < 4; e++) bsplit(stage[r][c8 + e],     h0v.v[e], l0v.v[e]);
#pragma unroll
                for (int e = 0; e < 4; e++) bsplit(stage[r][c8 + 4 + e], h1v.v[e], l1v.v[e]);
                *(BF4*)(Dhi + off)     = h0v;
                *(BF4*)(Dlo + off)     = l0v;
                *(BF4*)(Dhi + off + 4) = h1v;
                *(BF4*)(Dlo + off + 4) = l1v;
                __syncwarp();
            }
        return;
    }

#pragma unroll
    for (int i = 0; i < 2; i++)
#pragma unroll
        for (int j = 0; j < 4; j++) {
            int col = n0 + wn * 64 + j * 16;
            if (mode == 2) {
                int t = m0 >> 7;
                int b = wm * 32 + i * 16;
                float* p = D + (size_t)t * 1024 + (size_t)b * ((size_t)TN * 1024) + col;
                wmma::store_matrix_sync(p, acc[i][j], (unsigned)(TN * 1024), wmma::mem_row_major);
            } else {
                int row = m0 + wm * 32 + i * 16;
                wmma::store_matrix_sync(D + (size_t)row * N + col, acc[i][j], N, wmma::mem_row_major);
            }
        }
}

// ---------------- persistent recurrence v2: W_r resident in SMEM ----------------
// 128 CTAs x 256 thr, 1 CTA/SM, all co-resident. CTA owns 32 permuted cols.
// SMEM: WH [1024][40] 80K | WL 80K | A: 3 bufs x 20480 (hi[128][40]+lo)  = 225280 total.
// Warp (wm=wid>>1 in 0..3, wn=wid&1): M32 x N16 tile, 6 independent acc chains.
#define PS_WH 0
#define PS_WL 81920
#define PS_A  163840
#define PS_ABUF 20480
#define PS_TOTAL 225280

__device__ __forceinline__ void cp16(uint32_t dst, const void* src) {
    asm volatile("cp.async.cg.shared.global [%0], [%1], 16;" :: "r"(dst), "l"(src));
}
__device__ __forceinline__ void cp_commit() { asm volatile("cp.async.commit_group;"); }
template<int N> __device__ __forceinline__ void cp_wait() {
    asm volatile("cp.async.wait_group %0;" :: "n"(N));
}

__global__ __launch_bounds__(256, 1) void lstm_persist2(
    const __nv_bfloat16* __restrict__ Wh_g, const __nv_bfloat16* __restrict__ Wl_g)
{
    extern __shared__ char sm[];
    const uint32_t smb = (uint32_t)__cvta_generic_to_shared(sm);
    const int tid = threadIdx.x, wid = tid >> 5;
    const int bx = blockIdx.x;
    const int n0g = bx * 32;
    const int wm = wid >> 1, wn = wid & 1;

    // ---- load W block into smem once (conflict-free stride 40) ----
    for (int i = tid; i < 4096; i += 256) {
        int row = i >> 2, seg = (i & 3) * 8;
        cp16(smb + PS_WH + (uint32_t)(row * 40 + seg) * 2, Wh_g + (size_t)row * 4096 + n0g + seg);
        cp16(smb + PS_WL + (uint32_t)(row * 40 + seg) * 2, Wl_g + (size_t)row * 4096 + n0g + seg);
    }
    cp_commit(); cp_wait<0>();
    __syncthreads();

    __nv_bfloat16 (*WH)[40] = (__nv_bfloat16 (*)[40])(sm + PS_WH);
    __nv_bfloat16 (*WL)[40] = (__nv_bfloat16 (*)[40])(sm + PS_WL);

    const int m = tid & 127, half = tid >> 7, pc = half * 16;
    // c-state lives in registers for all 512 steps
    float cv[4];
    {
        float4 c4 = *(const float4*)(g_C + (size_t)m * UN + bx * 8 + half * 4);
        cv[0] = c4.x; cv[1] = c4.y; cv[2] = c4.z; cv[3] = c4.w;
    }
    const int arow = tid >> 1, aseg = (tid & 1) * 16;

    for (int t = 0; t < TN; t++) {
        const __nv_bfloat16* __restrict__ Hhi = g_Hhi + (size_t)t * (BSZ * UN);
        const __nv_bfloat16* __restrict__ Hlo = g_Hlo + (size_t)t * (BSZ * UN);

        // ZK(t) into registers — LDG issued at step start, consumed at epilogue
        float zkf[16];
        {
            const float* zk = g_ZK + ((size_t)t * BSZ + m) * 4096 + n0g + pc;
#pragma unroll
            for (int q = 0; q < 4; q++) {
                float4 v = *(const float4*)(zk + q * 4);
                zkf[q * 4 + 0] = v.x; zkf[q * 4 + 1] = v.y;
                zkf[q * 4 + 2] = v.z; zkf[q * 4 + 3] = v.w;
            }
        }

        auto issueA = [&](int chunk) {
            int buf = chunk % 3;
            uint32_t ad = smb + PS_A + buf * PS_ABUF + (uint32_t)(arow * 40 + aseg) * 2;
            const __nv_bfloat16* sh = Hhi + (size_t)arow * 1024 + chunk * 32 + aseg;
            const __nv_bfloat16* sl = Hlo + (size_t)arow * 1024 + chunk * 32 + aseg;
            cp16(ad,          sh);
            cp16(ad + 16,     sh + 8);
            cp16(ad + 10240,      sl);
            cp16(ad + 10240 + 16, sl + 8);
            cp_commit();
        };

        wmma::fragment<wmma::accumulator, 16, 16, 16, float> a0[2], a1[2], a2[2];
#pragma unroll
        for (int i = 0; i < 2; i++) {
            wmma::fill_fragment(a0[i], 0.f);
            wmma::fill_fragment(a1[i], 0.f);
            wmma::fill_fragment(a2[i], 0.f);
        }

        issueA(0); issueA(1);
        for (int c = 0; c < 32; c++) {
            if (c < 31) cp_wait<1>(); else cp_wait<0>();
            __syncthreads();
            if (c + 2 < 32) issueA(c + 2);

            int buf = c % 3;
            __nv_bfloat16 (*Ah)[40] = (__nv_bfloat16 (*)[40])(sm + PS_A + buf * PS_ABUF);
            __nv_bfloat16 (*Al)[40] = (__nv_bfloat16 (*)[40])(sm + PS_A + buf * PS_ABUF + 10240);

#pragma unroll
            for (int s = 0; s < 2; s++) {
                int kkg = c * 32 + s * 16;
                wmma::fragment<wmma::matrix_b, 16, 16, 16, __nv_bfloat16, wmma::row_major> bh, bl;
                wmma::fragment<wmma::matrix_a, 16, 16, 16, __nv_bfloat16, wmma::row_major> ah0, ah1, al0, al1;
                wmma::load_matrix_sync(bh, &WH[kkg][wn * 16], 40);
                wmma::load_matrix_sync(bl, &WL[kkg][wn * 16], 40);
                wmma::load_matrix_sync(ah0, &Ah[wm * 32][s * 16], 40);
                wmma::load_matrix_sync(ah1, &Ah[wm * 32 + 16][s * 16], 40);
                wmma::load_matrix_sync(al0, &Al[wm * 32][s * 16], 40);
                wmma::load_matrix_sync(al1, &Al[wm * 32 + 16][s * 16], 40);
                // 6 independent accumulator chains
                wmma::mma_sync(a0[0], ah0, bh, a0[0]);
                wmma::mma_sync(a0[1], ah1, bh, a0[1]);
                wmma::mma_sync(a1[0], ah0, bl, a1[0]);
                wmma::mma_sync(a1[1], ah1, bl, a1[1]);
                wmma::mma_sync(a2[0], al0, bh, a2[0]);
                wmma::mma_sync(a2[1], al1, bh, a2[1]);
            }
        }

        // combine + stage z in smem (overlay A buffers)
        __syncthreads();
        float (*z)[36] = (float (*)[36])(sm + PS_A);
#pragma unroll
        for (int i = 0; i < 2; i++) {
#pragma unroll
            for (int e = 0; e < a0[0].num_elements; e++)
                a0[i].x[e] += a1[i].x[e] + a2[i].x[e];
            wmma::store_matrix_sync(&z[wm * 32 + i * 16][wn * 16], a0[i], 36, wmma::mem_row_major);
        }
        __syncthreads();

        // gate epilogue: thread -> row m, half -> 4 units (16 perm cols)
        BF4 hh, hl;
#pragma unroll
        for (int e = 0; e < 4; e++) {
            float zi = z[m][pc + e * 4 + 0] + zkf[e * 4 + 0];
            float zf = z[m][pc + e * 4 + 1] + zkf[e * 4 + 1];
            float zg = z[m][pc + e * 4 + 2] + zkf[e * 4 + 2];
            float zo = z[m][pc + e * 4 + 3] + zkf[e * 4 + 3];
            float si = 1.f / (1.f + __expf(-zi));
            float sf = 1.f / (1.f + __expf(-zf));
            float so = 1.f / (1.f + __expf(-zo));
            float cn = sf * cv[e] + si * tanhf(zg);
            float hn = so * tanhf(cn);
            cv[e] = cn;
            bsplit(hn, hh.v[e], hl.v[e]);
        }
        size_t ho = (size_t)(t + 1) * (BSZ * UN) + (size_t)m * UN + bx * 8 + half * 4;
        *(BF4*)(g_Hhi + ho) = hh;
        *(BF4*)(g_Hlo + ho) = hl;

        // grid barrier (all 128 CTAs co-resident by construction)
        __threadfence();
        __syncthreads();
        if (tid == 0) {
            atomicAdd(&g_count, 1);
            volatile int* gc = &g_count;
            int target = NCTA * (t + 1);
            while (*gc < target) __nanosleep(64);
        }
        __syncthreads();
    }
}

// ---------------- host ----------------
extern "C" void kernel_launch(void* const* d_in, const int* in_sizes, int n_in,
                              void* d_out, int out_size)
{
    const float* h0    = (const float*)d_in[0];
    const float* c0    = (const float*)d_in[1];
    const float* X     = (const float*)d_in[2];
    const float* W_emb = (const float*)d_in[3];
    const float* b_emb = (const float*)d_in[4];
    const float* W_k   = (const float*)d_in[5];
    const float* W_r   = (const float*)d_in[6];
    const float* b_r   = (const float*)d_in[7];
    const float* W_out = (const float*)d_in[8];
    const float* b_out = (const float*)d_in[9];
    (void)in_sizes; (void)n_in; (void)out_size;

    __nv_bfloat16 *pXhi, *pXlo, *pEhi, *pElo, *pHhi, *pHlo;
    __nv_bfloat16 *pWembh, *pWembl, *pWouth, *pWoutl, *pWkh, *pWkl, *pWrh, *pWrl;
    float *pZK;
    cudaGetSymbolAddress((void**)&pXhi, g_Xhi);
    cudaGetSymbolAddress((void**)&pXlo, g_Xlo);
    cudaGetSymbolAddress((void**)&pEhi, g_Ehi);
    cudaGetSymbolAddress((void**)&pElo, g_Elo);
    cudaGetSymbolAddress((void**)&pHhi, g_Hhi);
    cudaGetSymbolAddress((void**)&pHlo, g_Hlo);
    cudaGetSymbolAddress((void**)&pWembh, g_Wemb_hi);
    cudaGetSymbolAddress((void**)&pWembl, g_Wemb_lo);
    cudaGetSymbolAddress((void**)&pWouth, g_Wout_hi);
    cudaGetSymbolAddress((void**)&pWoutl, g_Wout_lo);
    cudaGetSymbolAddress((void**)&pWkh, g_Wk_hi);
    cudaGetSymbolAddress((void**)&pWkl, g_Wk_lo);
    cudaGetSymbolAddress((void**)&pWrh, g_Wr_hi);
    cudaGetSymbolAddress((void**)&pWrl, g_Wr_lo);
    cudaGetSymbolAddress((void**)&pZK, g_ZK);

    cudaFuncSetAttribute(lstm_persist2, cudaFuncAttributeMaxDynamicSharedMemorySize, PS_TOTAL);

    // 1. merged prep (also resets g_count for graph replay determinism)
    prep_all<<<PREP_BLOCKS, 256>>>(X, h0, c0, W_emb, W_out, W_k, W_r);

    // 2. E = relu(X @ W_emb + b_emb), bf16 split written directly
    {
        dim3 grid(1024 / 128, MROWS / 128);
        wgemm<<<grid, 256>>>(pXhi, pXlo, pWembh, pWembl, b_emb,
                             nullptr, pEhi, pElo, 1024, 0);
    }
    // 3. ZK = E @ W_k + b_r
    {
        dim3 grid(4096 / 128, MROWS / 128);
        wgemm<<<grid, 256>>>(pEhi, pElo, pWkh, pWkl, b_r,
                             pZK, nullptr, nullptr, 4096, 1);
    }

    // 4. recurrence: one persistent kernel, W_r in SMEM, grid barrier per step
    lstm_persist2<<<NCTA, 256, PS_TOTAL>>>(pWrh, pWrl);

    // 5. OUT = H @ W_out + b_out, scattered to [b][t][:]
    {
        dim3 grid(1024 / 128, MROWS / 128);
        wgemm<<<grid, 256>>>(pHhi + (size_t)BSZ * UN, pHlo + (size_t)BSZ * UN,
                             pWouth, pWoutl, b_out,
                             (float*)d_out, nullptr, nullptr, 1024, 2);
    }
}

// round 11
// speedup vs baseline: 1.1122x; 1.0660x over previous
#include <cuda_runtime.h>
#include <cuda_bf16.h>
#include <mma.h>
#include <cstdint>

using namespace nvcuda;

#define BSZ 128
#define TN  512
#define UN  1024
#define MROWS (TN * BSZ)   // 65536
#define NCTA 128

// ---------------- scratch (static device globals) ----------------
__device__ __nv_bfloat16 g_Xhi[(size_t)MROWS * UN];
__device__ __nv_bfloat16 g_Xlo[(size_t)MROWS * UN];
__device__ __nv_bfloat16 g_Ehi[(size_t)MROWS * UN];
__device__ __nv_bfloat16 g_Elo[(size_t)MROWS * UN];
__device__ float         g_ZK [(size_t)MROWS * 4 * UN];   // permuted cols p=u*4+g
__device__ float         g_C  [(size_t)BSZ * UN];
__device__ __nv_bfloat16 g_Hhi[(size_t)(TN + 1) * BSZ * UN];
__device__ __nv_bfloat16 g_Hlo[(size_t)(TN + 1) * BSZ * UN];
__device__ __nv_bfloat16 g_Wemb_hi[(size_t)UN * UN];
__device__ __nv_bfloat16 g_Wemb_lo[(size_t)UN * UN];
__device__ __nv_bfloat16 g_Wout_hi[(size_t)UN * UN];
__device__ __nv_bfloat16 g_Wout_lo[(size_t)UN * UN];
__device__ __nv_bfloat16 g_Wk_hi[(size_t)UN * 4 * UN];    // permuted cols
__device__ __nv_bfloat16 g_Wk_lo[(size_t)UN * 4 * UN];
__device__ __nv_bfloat16 g_Wr_hi[(size_t)UN * 4 * UN];    // permuted cols
__device__ __nv_bfloat16 g_Wr_lo[(size_t)UN * 4 * UN];
__device__ int           g_count;

struct __align__(8) BF4 { __nv_bfloat16 v[4]; };

__device__ __forceinline__ void bsplit(float v, __nv_bfloat16& h, __nv_bfloat16& l) {
    h = __float2bfloat16(v);
    l = __float2bfloat16(v - __bfloat162float(h));
}

__device__ __forceinline__ void cp16(uint32_t dst, const void* src) {
    asm volatile("cp.async.cg.shared.global [%0], [%1], 16;" :: "r"(dst), "l"(src));
}
__device__ __forceinline__ void cp_commit() { asm volatile("cp.async.commit_group;"); }
template<int N> __device__ __forceinline__ void cp_wait() {
    asm volatile("cp.async.wait_group %0;" :: "n"(N));
}

// ---------------- merged prep kernel ----------------
#define PREP_ST0   65536
#define PREP_WE0   66048
#define PREP_WO0   67072
#define PREP_WK0   68096
#define PREP_WR0   72192
#define PREP_BLOCKS 76288

__global__ __launch_bounds__(256) void prep_all(
    const float* __restrict__ X, const float* __restrict__ h0, const float* __restrict__ c0,
    const float* __restrict__ W_emb, const float* __restrict__ W_out,
    const float* __restrict__ W_k, const float* __restrict__ W_r)
{
    const int b = blockIdx.x, tid = threadIdx.x;
    if (b < PREP_ST0) {                    // split_X: 4 elems/thread
        size_t i = (size_t)b * 256 + tid;
        size_t e = i * 4;
        size_t r = e >> 10;
        int k = (int)(e & 1023);
        int bb = (int)(r & 127), t = (int)(r >> 7);
        float4 v = *(const float4*)(X + ((size_t)bb * 513 + (size_t)t) * 1024 + k);
        BF4 h, l;
        bsplit(v.x, h.v[0], l.v[0]); bsplit(v.y, h.v[1], l.v[1]);
        bsplit(v.z, h.v[2], l.v[2]); bsplit(v.w, h.v[3], l.v[3]);
        *(BF4*)(g_Xhi + e) = h;
        *(BF4*)(g_Xlo + e) = l;
    } else if (b < PREP_WE0) {             // init_state
        int i = (b - PREP_ST0) * 256 + tid;
        if (b == PREP_ST0 && tid == 0) g_count = 0;
        g_C[i] = c0[i];
        __nv_bfloat16 h, l; bsplit(h0[i], h, l);
        g_Hhi[i] = h; g_Hlo[i] = l;
    } else if (b < PREP_WK0) {             // W_emb / W_out (no perm)
        int isout = (b >= PREP_WO0);
        const float* W = isout ? W_out : W_emb;
        __nv_bfloat16* hi = isout ? g_Wout_hi : g_Wemb_hi;
        __nv_bfloat16* lo = isout ? g_Wout_lo : g_Wemb_lo;
        size_t q = (size_t)(b - (isout ? PREP_WO0 : PREP_WE0)) * 256 + tid;
        size_t e = q * 4;
        float4 v = *(const float4*)(W + e);
        BF4 h, l;
        bsplit(v.x, h.v[0], l.v[0]); bsplit(v.y, h.v[1], l.v[1]);
        bsplit(v.z, h.v[2], l.v[2]); bsplit(v.w, h.v[3], l.v[3]);
        *(BF4*)(hi + e) = h;
        *(BF4*)(lo + e) = l;
    } else {                               // W_k / W_r permuted
        int isr = (b >= PREP_WR0);
        const float* W = isr ? W_r : W_k;
        __nv_bfloat16* hi = isr ? g_Wr_hi : g_Wk_hi;
        __nv_bfloat16* lo = isr ? g_Wr_lo : g_Wk_lo;
        size_t q = (size_t)(b - (isr ? PREP_WR0 : PREP_WK0)) * 256 + tid;
        int row = (int)(q >> 10);
        int qc = (int)(q & 1023);
        const float* src = W + (size_t)row * 4096 + qc;
        BF4 h, l;
        bsplit(src[0],    h.v[0], l.v[0]);
        bsplit(src[1024], h.v[1], l.v[1]);
        bsplit(src[2048], h.v[2], l.v[2]);
        bsplit(src[3072], h.v[3], l.v[3]);
        size_t e = (size_t)row * 4096 + (size_t)qc * 4;
        *(BF4*)(hi + e) = h;
        *(BF4*)(lo + e) = l;
    }
}

// ---------------- bf16-split wmma GEMM v2: 2-buffer cp.async pipeline ----------------
// smem layout per buf (37888B): Ahi[128][40] 10240 | Alo 10240 | Bhi[32][136] 8704 | Blo 8704
// bufs at 0, 37888; sbias/stage at 75776 (8192B). Total 83968 -> 2 CTAs/SM.
#define WG_BUF   37888
#define WG_BIAS  75776
#define WG_TOTAL 83968

__global__ __launch_bounds__(256) void wgemm(
    const __nv_bfloat16* __restrict__ Ahi, const __nv_bfloat16* __restrict__ Alo,
    const __nv_bfloat16* __restrict__ Bhi, const __nv_bfloat16* __restrict__ Blo,
    const float* __restrict__ bias, float* __restrict__ D,
    __nv_bfloat16* __restrict__ Dhi, __nv_bfloat16* __restrict__ Dlo,
    int N, int mode)
{
    extern __shared__ char sm[];
    const uint32_t smb = (uint32_t)__cvta_generic_to_shared(sm);

    const int tid = threadIdx.x;
    const int n0 = blockIdx.x * 128, m0 = blockIdx.y * 128;
    const int wid = tid >> 5, lane = tid & 31;
    const int wm = wid & 3, wn = wid >> 2;

    float (*sbias)[128] = (float (*)[128])(sm + WG_BIAS);
    for (int i = tid; i < 2048; i += 256) {
        int col = i & 127;
        int p = n0 + col;
        float bv = (mode == 1) ? bias[(p & 3) * 1024 + (p >> 2)] : bias[p];
        sbias[i >> 7][col] = bv;
    }
    __syncthreads();

    wmma::fragment<wmma::accumulator, 16, 16, 16, float> acc[2][4];
#pragma unroll
    for (int i = 0; i < 2; i++)
#pragma unroll
        for (int j = 0; j < 4; j++)
            wmma::load_matrix_sync(acc[i][j], &sbias[0][wn * 64 + j * 16], 128, wmma::mem_row_major);
    __syncthreads();

    // cp.async mappings: A: 128 rows x 32 cols hi+lo; B: 32 rows x 128 cols hi+lo
    const int arow = tid >> 1, aseg = (tid & 1) * 16;
    const int brow = tid >> 3, bseg = (tid & 7) * 16;

    auto issue = [&](int c) {
        uint32_t base = smb + (uint32_t)(c & 1) * WG_BUF;
        int k0 = c * 32;
        uint32_t ad = base + (uint32_t)(arow * 40 + aseg) * 2;
        const __nv_bfloat16* sh = Ahi + (size_t)(m0 + arow) * 1024 + k0 + aseg;
        const __nv_bfloat16* sl = Alo + (size_t)(m0 + arow) * 1024 + k0 + aseg;
        cp16(ad,              sh);
        cp16(ad + 16,         sh + 8);
        cp16(ad + 10240,      sl);
        cp16(ad + 10240 + 16, sl + 8);
        uint32_t bd = base + 20480 + (uint32_t)(brow * 136 + bseg) * 2;
        const __nv_bfloat16* bhp = Bhi + (size_t)(k0 + brow) * N + n0 + bseg;
        const __nv_bfloat16* blp = Blo + (size_t)(k0 + brow) * N + n0 + bseg;
        cp16(bd,             bhp);
        cp16(bd + 16,        bhp + 8);
        cp16(bd + 8704,      blp);
        cp16(bd + 8704 + 16, blp + 8);
        cp_commit();
    };

    issue(0);
    for (int c = 0; c < 32; c++) {
        cp_wait<0>();
        __syncthreads();          // chunk c visible; prev compute done -> other buf free
        if (c + 1 < 32) issue(c + 1);

        char* bufp = sm + (c & 1) * WG_BUF;
        __nv_bfloat16 (*sAhi)[40]  = (__nv_bfloat16 (*)[40])(bufp);
        __nv_bfloat16 (*sAlo)[40]  = (__nv_bfloat16 (*)[40])(bufp + 10240);
        __nv_bfloat16 (*sBhi)[136] = (__nv_bfloat16 (*)[136])(bufp + 20480);
        __nv_bfloat16 (*sBlo)[136] = (__nv_bfloat16 (*)[136])(bufp + 20480 + 8704);

#pragma unroll
        for (int kk = 0; kk < 32; kk += 16) {
            wmma::fragment<wmma::matrix_a, 16, 16, 16, __nv_bfloat16, wmma::row_major> ah[2], al[2];
            wmma::fragment<wmma::matrix_b, 16, 16, 16, __nv_bfloat16, wmma::row_major> bh[4], bl[4];
#pragma unroll
            for (int i = 0; i < 2; i++) {
                wmma::load_matrix_sync(ah[i], &sAhi[wm * 32 + i * 16][kk], 40);
                wmma::load_matrix_sync(al[i], &sAlo[wm * 32 + i * 16][kk], 40);
            }
#pragma unroll
            for (int j = 0; j < 4; j++) {
                wmma::load_matrix_sync(bh[j], &sBhi[kk][wn * 64 + j * 16], 136);
                wmma::load_matrix_sync(bl[j], &sBlo[kk][wn * 64 + j * 16], 136);
            }
#pragma unroll
            for (int i = 0; i < 2; i++)
#pragma unroll
                for (int j = 0; j < 4; j++) {
                    wmma::mma_sync(acc[i][j], ah[i], bh[j], acc[i][j]);
                    wmma::mma_sync(acc[i][j], ah[i], bl[j], acc[i][j]);
                    wmma::mma_sync(acc[i][j], al[i], bh[j], acc[i][j]);
                }
        }
    }

    if (mode == 0) {
        float (*stage)[16] = (float (*)[16])((float*)(sm + WG_BIAS) + wid * 256);
        __syncthreads();
#pragma unroll
        for (int i = 0; i < 2; i++)
#pragma unroll
            for (int j = 0; j < 4; j++) {
                for (int e = 0; e < acc[i][j].num_elements; e++)
                    acc[i][j].x[e] = fmaxf(acc[i][j].x[e], 0.f);
                wmma::store_matrix_sync(&stage[0][0], acc[i][j], 16, wmma::mem_row_major);
                __syncwarp();
                int r = lane & 15, c8 = (lane >> 4) * 8;
                size_t row = (size_t)(m0 + wm * 32 + i * 16 + r);
                size_t off = row * 1024 + (n0 + wn * 64 + j * 16 + c8);
                BF4 h0v, l0v, h1v, l1v;
#pragma unroll
                for (int e = 0; e < 4; e++) bsplit(stage[r][c8 + e],     h0v.v[e], l0v.v[e]);
#pragma unroll
                for (int e = 0; e < 4; e++) bsplit(stage[r][c8 + 4 + e], h1v.v[e], l1v.v[e]);
                *(BF4*)(Dhi + off)     = h0v;
                *(BF4*)(Dlo + off)     = l0v;
                *(BF4*)(Dhi + off + 4) = h1v;
                *(BF4*)(Dlo + off + 4) = l1v;
                __syncwarp();
            }
        return;
    }

#pragma unroll
    for (int i = 0; i < 2; i++)
#pragma unroll
        for (int j = 0; j < 4; j++) {
            int col = n0 + wn * 64 + j * 16;
            if (mode == 2) {
                int t = m0 >> 7;
                int b = wm * 32 + i * 16;
                float* p = D + (size_t)t * 1024 + (size_t)b * ((size_t)TN * 1024) + col;
                wmma::store_matrix_sync(p, acc[i][j], (unsigned)(TN * 1024), wmma::mem_row_major);
            } else {
                int row = m0 + wm * 32 + i * 16;
                wmma::store_matrix_sync(D + (size_t)row * N + col, acc[i][j], N, wmma::mem_row_major);
            }
        }
}

// ---------------- persistent recurrence v3: 512 thr, K-split warp groups ----------------
// 128 CTAs x 512 thr, 1 CTA/SM. CTA owns 32 permuted cols.
// SMEM: WH [1024][40] 80K | WL 80K | A: 3 bufs x 20480 (hi[128][40]+lo).
// 16 warps: group g=wid>>3 handles k-half g*16 of each 32-chunk; warp tile M32xN16,
// 6 indep acc chains. Two partial z buffers (one per group) summed in epilogue.
#define PS_WH 0
#define PS_WL 81920
#define PS_A  163840
#define PS_ABUF 20480
#define PS_TOTAL 225280

__global__ __launch_bounds__(512, 1) void lstm_persist3(
    const __nv_bfloat16* __restrict__ Wh_g, const __nv_bfloat16* __restrict__ Wl_g)
{
    extern __shared__ char sm[];
    const uint32_t smb = (uint32_t)__cvta_generic_to_shared(sm);
    const int tid = threadIdx.x, wid = tid >> 5;
    const int bx = blockIdx.x;
    const int n0g = bx * 32;
    const int g = wid >> 3, w8 = wid & 7;
    const int wm = w8 >> 1, wn = w8 & 1;

    // ---- load W block into smem once (conflict-free stride 40) ----
    for (int i = tid; i < 4096; i += 512) {
        int row = i >> 2, seg = (i & 3) * 8;
        cp16(smb + PS_WH + (uint32_t)(row * 40 + seg) * 2, Wh_g + (size_t)row * 4096 + n0g + seg);
        cp16(smb + PS_WL + (uint32_t)(row * 40 + seg) * 2, Wl_g + (size_t)row * 4096 + n0g + seg);
    }
    cp_commit(); cp_wait<0>();
    __syncthreads();

    __nv_bfloat16 (*WH)[40] = (__nv_bfloat16 (*)[40])(sm + PS_WH);
    __nv_bfloat16 (*WL)[40] = (__nv_bfloat16 (*)[40])(sm + PS_WL);

    const int m = tid & 127, grp = tid >> 7;       // grp 0..3 -> 2 units (8 perm cols)
    const int pc = grp * 8;
    float cv[2];
    {
        float2 c2 = *(const float2*)(g_C + (size_t)m * UN + bx * 8 + grp * 2);
        cv[0] = c2.x; cv[1] = c2.y;
    }
    const int arow = tid >> 2, aseg = (tid & 3) * 8;   // 512 thr: 1 cp16 hi + 1 lo each

    for (int t = 0; t < TN; t++) {
        const __nv_bfloat16* __restrict__ Hhi = g_Hhi + (size_t)t * (BSZ * UN);
        const __nv_bfloat16* __restrict__ Hlo = g_Hlo + (size_t)t * (BSZ * UN);

        // ZK(t) into registers early (DRAM latency hidden behind mainloop)
        float zkf[8];
        {
            const float* zk = g_ZK + ((size_t)t * BSZ + m) * 4096 + n0g + pc;
            float4 v0 = *(const float4*)(zk);
            float4 v1 = *(const float4*)(zk + 4);
            zkf[0] = v0.x; zkf[1] = v0.y; zkf[2] = v0.z; zkf[3] = v0.w;
            zkf[4] = v1.x; zkf[5] = v1.y; zkf[6] = v1.z; zkf[7] = v1.w;
        }

        auto issueA = [&](int chunk) {
            int buf = chunk % 3;
            uint32_t ad = smb + PS_A + buf * PS_ABUF + (uint32_t)(arow * 40 + aseg) * 2;
            cp16(ad,         Hhi + (size_t)arow * 1024 + chunk * 32 + aseg);
            cp16(ad + 10240, Hlo + (size_t)arow * 1024 + chunk * 32 + aseg);
            cp_commit();
        };

        wmma::fragment<wmma::accumulator, 16, 16, 16, float> a0[2], a1[2], a2[2];
#pragma unroll
        for (int i = 0; i < 2; i++) {
            wmma::fill_fragment(a0[i], 0.f);
            wmma::fill_fragment(a1[i], 0.f);
            wmma::fill_fragment(a2[i], 0.f);
        }

        issueA(0); issueA(1);
        for (int c = 0; c < 32; c++) {
            if (c < 31) cp_wait<1>(); else cp_wait<0>();
            __syncthreads();
            if (c + 2 < 32) issueA(c + 2);

            int buf = c % 3;
            __nv_bfloat16 (*Ah)[40] = (__nv_bfloat16 (*)[40])(sm + PS_A + buf * PS_ABUF);
            __nv_bfloat16 (*Al)[40] = (__nv_bfloat16 (*)[40])(sm + PS_A + buf * PS_ABUF + 10240);

            const int kkg = c * 32 + g * 16;       // group's k-half of this chunk
            const int ka = g * 16;
            wmma::fragment<wmma::matrix_b, 16, 16, 16, __nv_bfloat16, wmma::row_major> bh, bl;
            wmma::fragment<wmma::matrix_a, 16, 16, 16, __nv_bfloat16, wmma::row_major> ah0, ah1, al0, al1;
            wmma::load_matrix_sync(bh, &WH[kkg][wn * 16], 40);
            wmma::load_matrix_sync(bl, &WL[kkg][wn * 16], 40);
            wmma::load_matrix_sync(ah0, &Ah[wm * 32][ka], 40);
            wmma::load_matrix_sync(ah1, &Ah[wm * 32 + 16][ka], 40);
            wmma::load_matrix_sync(al0, &Al[wm * 32][ka], 40);
            wmma::load_matrix_sync(al1, &Al[wm * 32 + 16][ka], 40);
            // 6 independent accumulator chains
            wmma::mma_sync(a0[0], ah0, bh, a0[0]);
            wmma::mma_sync(a0[1], ah1, bh, a0[1]);
            wmma::mma_sync(a1[0], ah0, bl, a1[0]);
            wmma::mma_sync(a1[1], ah1, bl, a1[1]);
            wmma::mma_sync(a2[0], al0, bh, a2[0]);
            wmma::mma_sync(a2[1], al1, bh, a2[1]);
        }

        // partial z per group -> two smem buffers (overlay A buffers)
        __syncthreads();
        float (*zp)[36] = (float (*)[36])(sm + PS_A + g * 18432);
#pragma unroll
        for (int i = 0; i < 2; i++) {
#pragma unroll
            for (int e = 0; e < a0[0].num_elements; e++)
                a0[i].x[e] += a1[i].x[e] + a2[i].x[e];
            wmma::store_matrix_sync(&zp[wm * 32 + i * 16][wn * 16], a0[i], 36, wmma::mem_row_major);
        }
        __syncthreads();

        // gate epilogue: thread -> row m, 2 units
        float (*z0)[36] = (float (*)[36])(sm + PS_A);
        float (*z1)[36] = (float (*)[36])(sm + PS_A + 18432);
        __nv_bfloat162 hh2, hl2;
#pragma unroll
        for (int e = 0; e < 2; e++) {
            float zi = z0[m][pc + e * 4 + 0] + z1[m][pc + e * 4 + 0] + zkf[e * 4 + 0];
            float zf = z0[m][pc + e * 4 + 1] + z1[m][pc + e * 4 + 1] + zkf[e * 4 + 1];
            float zg = z0[m][pc + e * 4 + 2] + z1[m][pc + e * 4 + 2] + zkf[e * 4 + 2];
            float zo = z0[m][pc + e * 4 + 3] + z1[m][pc + e * 4 + 3] + zkf[e * 4 + 3];
            float si = 1.f / (1.f + __expf(-zi));
            float sf = 1.f / (1.f + __expf(-zf));
            float so = 1.f / (1.f + __expf(-zo));
            float cn = sf * cv[e] + si * tanhf(zg);
            float hn = so * tanhf(cn);
            cv[e] = cn;
            __nv_bfloat16 h, l; bsplit(hn, h, l);
            if (e == 0) { hh2.x = h; hl2.x = l; } else { hh2.y = h; hl2.y = l; }
        }
        size_t ho = (size_t)(t + 1) * (BSZ * UN) + (size_t)m * UN + bx * 8 + grp * 2;
        *(__nv_bfloat162*)(g_Hhi + ho) = hh2;
        *(__nv_bfloat162*)(g_Hlo + ho) = hl2;

        // grid barrier (all 128 CTAs co-resident)
        __threadfence();
        __syncthreads();
        if (tid == 0) {
            atomicAdd(&g_count, 1);
            volatile int* gc = &g_count;
            int target = NCTA * (t + 1);
            while (*gc < target) __nanosleep(64);
        }
        __syncthreads();
    }
}

// ---------------- host ----------------
extern "C" void kernel_launch(void* const* d_in, const int* in_sizes, int n_in,
                              void* d_out, int out_size)
{
    const float* h0    = (const float*)d_in[0];
    const float* c0    = (const float*)d_in[1];
    const float* X     = (const float*)d_in[2];
    const float* W_emb = (const float*)d_in[3];
    const float* b_emb = (const float*)d_in[4];
    const float* W_k   = (const float*)d_in[5];
    const float* W_r   = (const float*)d_in[6];
    const float* b_r   = (const float*)d_in[7];
    const float* W_out = (const float*)d_in[8];
    const float* b_out = (const float*)d_in[9];
    (void)in_sizes; (void)n_in; (void)out_size;

    __nv_bfloat16 *pXhi, *pXlo, *pEhi, *pElo, *pHhi, *pHlo;
    __nv_bfloat16 *pWembh, *pWembl, *pWouth, *pWoutl, *pWkh, *pWkl, *pWrh, *pWrl;
    float *pZK;
    cudaGetSymbolAddress((void**)&pXhi, g_Xhi);
    cudaGetSymbolAddress((void**)&pXlo, g_Xlo);
    cudaGetSymbolAddress((void**)&pEhi, g_Ehi);
    cudaGetSymbolAddress((void**)&pElo, g_Elo);
    cudaGetSymbolAddress((void**)&pHhi, g_Hhi);
    cudaGetSymbolAddress((void**)&pHlo, g_Hlo);
    cudaGetSymbolAddress((void**)&pWembh, g_Wemb_hi);
    cudaGetSymbolAddress((void**)&pWembl, g_Wemb_lo);
    cudaGetSymbolAddress((void**)&pWouth, g_Wout_hi);
    cudaGetSymbolAddress((void**)&pWoutl, g_Wout_lo);
    cudaGetSymbolAddress((void**)&pWkh, g_Wk_hi);
    cudaGetSymbolAddress((void**)&pWkl, g_Wk_lo);
    cudaGetSymbolAddress((void**)&pWrh, g_Wr_hi);
    cudaGetSymbolAddress((void**)&pWrl, g_Wr_lo);
    cudaGetSymbolAddress((void**)&pZK, g_ZK);

    cudaFuncSetAttribute(wgemm, cudaFuncAttributeMaxDynamicSharedMemorySize, WG_TOTAL);
    cudaFuncSetAttribute(lstm_persist3, cudaFuncAttributeMaxDynamicSharedMemorySize, PS_TOTAL);

    // 1. merged prep (also resets g_count each launch)
    prep_all<<<PREP_BLOCKS, 256>>>(X, h0, c0, W_emb, W_out, W_k, W_r);

    // 2. E = relu(X @ W_emb + b_emb), bf16 split written directly
    {
        dim3 grid(1024 / 128, MROWS / 128);
        wgemm<<<grid, 256, WG_TOTAL>>>(pXhi, pXlo, pWembh, pWembl, b_emb,
                                       nullptr, pEhi, pElo, 1024, 0);
    }
    // 3. ZK = E @ W_k + b_r
    {
        dim3 grid(4096 / 128, MROWS / 128);
        wgemm<<<grid, 256, WG_TOTAL>>>(pEhi, pElo, pWkh, pWkl, b_r,
                                       pZK, nullptr, nullptr, 4096, 1);
    }

    // 4. recurrence: persistent kernel, W in SMEM, 16 warps K-split
    lstm_persist3<<<NCTA, 512, PS_TOTAL>>>(pWrh, pWrl);

    // 5. OUT = H @ W_out + b_out, scattered to [b][t][:]
    {
        dim3 grid(1024 / 128, MROWS / 128);
        wgemm<<<grid, 256, WG_TOTAL>>>(pHhi + (size_t)BSZ * UN, pHlo + (size_t)BSZ * UN,
                                       pWouth, pWoutl, b_out,
                                       (float*)d_out, nullptr, nullptr, 1024, 2);
    }
}

// round 12
// speedup vs baseline: 1.6705x; 1.5020x over previous
#include <cuda_runtime.h>
#include <cuda_fp16.h>
#include <mma.h>
#include <cstdint>

using namespace nvcuda;

#define BSZ 128
#define TN  512
#define UN  1024
#define MROWS (TN * BSZ)   // 65536
#define NCTA 128
#define INV256 0.00390625f

// ---------------- scratch (static device globals) ----------------
__device__ __half g_Xh [(size_t)MROWS * UN];
__device__ __half g_Eh [(size_t)MROWS * UN];
__device__ float  g_ZK [(size_t)MROWS * 4 * UN];   // permuted cols p=u*4+g
__device__ float  g_C  [(size_t)BSZ * UN];
__device__ __half g_Hhi[(size_t)(TN + 1) * BSZ * UN];
__device__ __half g_Hlo[(size_t)(TN + 1) * BSZ * UN];   // stored x256
__device__ __half g_Wemb_hi[(size_t)UN * UN];
__device__ __half g_Wemb_lo[(size_t)UN * UN];           // x256
__device__ __half g_Wout_hi[(size_t)UN * UN];
__device__ __half g_Wout_lo[(size_t)UN * UN];           // x256
__device__ __half g_Wk_hi[(size_t)UN * 4 * UN];         // permuted cols
__device__ __half g_Wk_lo[(size_t)UN * 4 * UN];         // x256
__device__ __half g_Wr_hi[(size_t)UN * 4 * UN];         // permuted cols
__device__ __half g_Wr_lo[(size_t)UN * 4 * UN];         // x256
__device__ int    g_count;

struct __align__(8) H4 { __half v[4]; };

__device__ __forceinline__ void hsplit(float v, __half& h, __half& l) {
    h = __float2half_rn(v);
    l = __float2half_rn((v - __half2float(h)) * 256.0f);
}

__device__ __forceinline__ void cp16(uint32_t dst, const void* src) {
    asm volatile("cp.async.cg.shared.global [%0], [%1], 16;" :: "r"(dst), "l"(src));
}
__device__ __forceinline__ void cp_commit() { asm volatile("cp.async.commit_group;"); }
template<int N> __device__ __forceinline__ void cp_wait() {
    asm volatile("cp.async.wait_group %0;" :: "n"(N));
}

// ---------------- merged prep kernel ----------------
#define PREP_ST0   65536
#define PREP_WE0   66048
#define PREP_WO0   67072
#define PREP_WK0   68096
#define PREP_WR0   72192
#define PREP_BLOCKS 76288

__global__ __launch_bounds__(256) void prep_all(
    const float* __restrict__ X, const float* __restrict__ h0, const float* __restrict__ c0,
    const float* __restrict__ W_emb, const float* __restrict__ W_out,
    const float* __restrict__ W_k, const float* __restrict__ W_r)
{
    const int b = blockIdx.x, tid = threadIdx.x;
    if (b < PREP_ST0) {                    // X -> fp16 (hi only), 4 elems/thread
        size_t i = (size_t)b * 256 + tid;
        size_t e = i * 4;
        size_t r = e >> 10;
        int k = (int)(e & 1023);
        int bb = (int)(r & 127), t = (int)(r >> 7);
        float4 v = *(const float4*)(X + ((size_t)bb * 513 + (size_t)t) * 1024 + k);
        H4 h;
        h.v[0] = __float2half_rn(v.x); h.v[1] = __float2half_rn(v.y);
        h.v[2] = __float2half_rn(v.z); h.v[3] = __float2half_rn(v.w);
        *(H4*)(g_Xh + e) = h;
    } else if (b < PREP_WE0) {             // init_state
        int i = (b - PREP_ST0) * 256 + tid;
        if (b == PREP_ST0 && tid == 0) g_count = 0;
        g_C[i] = c0[i];
        __half h, l; hsplit(h0[i], h, l);
        g_Hhi[i] = h; g_Hlo[i] = l;
    } else if (b < PREP_WK0) {             // W_emb / W_out split (no perm), lo x256
        int isout = (b >= PREP_WO0);
        const float* W = isout ? W_out : W_emb;
        __half* hi = isout ? g_Wout_hi : g_Wemb_hi;
        __half* lo = isout ? g_Wout_lo : g_Wemb_lo;
        size_t q = (size_t)(b - (isout ? PREP_WO0 : PREP_WE0)) * 256 + tid;
        size_t e = q * 4;
        float4 v = *(const float4*)(W + e);
        H4 h, l;
        hsplit(v.x, h.v[0], l.v[0]); hsplit(v.y, h.v[1], l.v[1]);
        hsplit(v.z, h.v[2], l.v[2]); hsplit(v.w, h.v[3], l.v[3]);
        *(H4*)(hi + e) = h;
        *(H4*)(lo + e) = l;
    } else {                               // W_k / W_r permuted split, lo x256
        int isr = (b >= PREP_WR0);
        const float* W = isr ? W_r : W_k;
        __half* hi = isr ? g_Wr_hi : g_Wk_hi;
        __half* lo = isr ? g_Wr_lo : g_Wk_lo;
        size_t q = (size_t)(b - (isr ? PREP_WR0 : PREP_WK0)) * 256 + tid;
        int row = (int)(q >> 10);
        int qc = (int)(q & 1023);
        const float* src = W + (size_t)row * 4096 + qc;
        H4 h, l;
        hsplit(src[0],    h.v[0], l.v[0]);
        hsplit(src[1024], h.v[1], l.v[1]);
        hsplit(src[2048], h.v[2], l.v[2]);
        hsplit(src[3072], h.v[3], l.v[3]);
        size_t e = (size_t)row * 4096 + (size_t)qc * 4;
        *(H4*)(hi + e) = h;
        *(H4*)(lo + e) = l;
    }
}

// ---------------- fp16 2-term wmma GEMM, 2-buffer cp.async pipeline ----------------
// D = A(fp16) @ (Bhi + Blo/256) + bias  — cross term via Ahi/256 shadow fragment.
// mode 0: relu, write fp16 D (g_Eh). mode 1: fp32 D, perm bias. mode 2: d_out scatter.
// smem per buf (27648B): A[128][40] 10240 | Bhi[32][136] 8704 | Blo 8704
#define WG_BUF   27648
#define WG_BIAS  55296
#define WG_TOTAL 63488

__global__ __launch_bounds__(256) void wgemm(
    const __half* __restrict__ A,
    const __half* __restrict__ Bhi, const __half* __restrict__ Blo,
    const float* __restrict__ bias, float* __restrict__ D,
    __half* __restrict__ Dh,
    int N, int mode)
{
    extern __shared__ char sm[];
    const uint32_t smb = (uint32_t)__cvta_generic_to_shared(sm);

    const int tid = threadIdx.x;
    const int n0 = blockIdx.x * 128, m0 = blockIdx.y * 128;
    const int wid = tid >> 5, lane = tid & 31;
    const int wm = wid & 3, wn = wid >> 2;

    float (*sbias)[128] = (float (*)[128])(sm + WG_BIAS);
    for (int i = tid; i < 2048; i += 256) {
        int col = i & 127;
        int p = n0 + col;
        float bv = (mode == 1) ? bias[(p & 3) * 1024 + (p >> 2)] : bias[p];
        sbias[i >> 7][col] = bv;
    }
    __syncthreads();

    wmma::fragment<wmma::accumulator, 16, 16, 16, float> acc[2][4];
#pragma unroll
    for (int i = 0; i < 2; i++)
#pragma unroll
        for (int j = 0; j < 4; j++)
            wmma::load_matrix_sync(acc[i][j], &sbias[0][wn * 64 + j * 16], 128, wmma::mem_row_major);
    __syncthreads();

    // cp.async: A chunk 128x32 fp16 = 8KB (2 cp16/thread); B hi+lo each 32x128 fp16
    const int arow = tid >> 1, aseg = (tid & 1) * 16;
    const int brow = tid >> 3, bseg = (tid & 7) * 16;

    auto issue = [&](int c) {
        uint32_t base = smb + (uint32_t)(c & 1) * WG_BUF;
        int k0 = c * 32;
        uint32_t ad = base + (uint32_t)(arow * 40 + aseg) * 2;
        const __half* ap = A + (size_t)(m0 + arow) * 1024 + k0 + aseg;
        cp16(ad,      ap);
        cp16(ad + 16, ap + 8);
        uint32_t bd = base + 10240 + (uint32_t)(brow * 136 + bseg) * 2;
        const __half* bhp = Bhi + (size_t)(k0 + brow) * N + n0 + bseg;
        const __half* blp = Blo + (size_t)(k0 + brow) * N + n0 + bseg;
        cp16(bd,             bhp);
        cp16(bd + 16,        bhp + 8);
        cp16(bd + 8704,      blp);
        cp16(bd + 8704 + 16, blp + 8);
        cp_commit();
    };

    const __half hinv = __float2half_rn(INV256);

    issue(0);
    for (int c = 0; c < 32; c++) {
        cp_wait<0>();
        __syncthreads();
        if (c + 1 < 32) issue(c + 1);

        char* bufp = sm + (c & 1) * WG_BUF;
        __half (*sA)[40]   = (__half (*)[40])(bufp);
        __half (*sBhi)[136] = (__half (*)[136])(bufp + 10240);
        __half (*sBlo)[136] = (__half (*)[136])(bufp + 10240 + 8704);

#pragma unroll
        for (int kk = 0; kk < 32; kk += 16) {
            wmma::fragment<wmma::matrix_a, 16, 16, 16, __half, wmma::row_major> ah[2], ahs[2];
            wmma::fragment<wmma::matrix_b, 16, 16, 16, __half, wmma::row_major> bh[4], bl[4];
#pragma unroll
            for (int i = 0; i < 2; i++) {
                wmma::load_matrix_sync(ah[i], &sA[wm * 32 + i * 16][kk], 40);
#pragma unroll
                for (int e = 0; e < ah[i].num_elements; e++)
                    ahs[i].x[e] = __hmul(ah[i].x[e], hinv);
            }
#pragma unroll
            for (int j = 0; j < 4; j++) {
                wmma::load_matrix_sync(bh[j], &sBhi[kk][wn * 64 + j * 16], 136);
                wmma::load_matrix_sync(bl[j], &sBlo[kk][wn * 64 + j * 16], 136);
            }
#pragma unroll
            for (int i = 0; i < 2; i++)
#pragma unroll
                for (int j = 0; j < 4; j++) {
                    wmma::mma_sync(acc[i][j], ah[i],  bh[j], acc[i][j]);
                    wmma::mma_sync(acc[i][j], ahs[i], bl[j], acc[i][j]);
                }
        }
    }

    if (mode == 0) {
        float (*stage)[16] = (float (*)[16])((float*)(sm + WG_BIAS) + wid * 256);
        __syncthreads();
#pragma unroll
        for (int i = 0; i < 2; i++)
#pragma unroll
            for (int j = 0; j < 4; j++) {
                for (int e = 0; e < acc[i][j].num_elements; e++)
                    acc[i][j].x[e] = fmaxf(acc[i][j].x[e], 0.f);
                wmma::store_matrix_sync(&stage[0][0], acc[i][j], 16, wmma::mem_row_major);
                __syncwarp();
                int r = lane & 15, c8 = (lane >> 4) * 8;
                size_t row = (size_t)(m0 + wm * 32 + i * 16 + r);
                size_t off = row * 1024 + (n0 + wn * 64 + j * 16 + c8);
                H4 h0v, h1v;
#pragma unroll
                for (int e = 0; e < 4; e++) h0v.v[e] = __float2half_rn(stage[r][c8 + e]);
#pragma unroll
                for (int e = 0; e < 4; e++) h1v.v[e] = __float2half_rn(stage[r][c8 + 4 + e]);
                *(H4*)(Dh + off)     = h0v;
                *(H4*)(Dh + off + 4) = h1v;
                __syncwarp();
            }
        return;
    }

#pragma unroll
    for (int i = 0; i < 2; i++)
#pragma unroll
        for (int j = 0; j < 4; j++) {
            int col = n0 + wn * 64 + j * 16;
            if (mode == 2) {
                int t = m0 >> 7;
                int b = wm * 32 + i * 16;
                float* p = D + (size_t)t * 1024 + (size_t)b * ((size_t)TN * 1024) + col;
                wmma::store_matrix_sync(p, acc[i][j], (unsigned)(TN * 1024), wmma::mem_row_major);
            } else {
                int row = m0 + wm * 32 + i * 16;
                wmma::store_matrix_sync(D + (size_t)row * N + col, acc[i][j], N, wmma::mem_row_major);
            }
        }
}

// ---------------- persistent recurrence: fp16 3-term, W in SMEM, 16 warps K-split ----------------
#define PS_WH 0
#define PS_WL 81920
#define PS_A  163840
#define PS_ABUF 20480
#define PS_TOTAL 225280

__global__ __launch_bounds__(512, 1) void lstm_persist4(
    const __half* __restrict__ Wh_g, const __half* __restrict__ Wl_g)
{
    extern __shared__ char sm[];
    const uint32_t smb = (uint32_t)__cvta_generic_to_shared(sm);
    const int tid = threadIdx.x, wid = tid >> 5;
    const int bx = blockIdx.x;
    const int n0g = bx * 32;
    const int g = wid >> 3, w8 = wid & 7;
    const int wm = w8 >> 1, wn = w8 & 1;

    for (int i = tid; i < 4096; i += 512) {
        int row = i >> 2, seg = (i & 3) * 8;
        cp16(smb + PS_WH + (uint32_t)(row * 40 + seg) * 2, Wh_g + (size_t)row * 4096 + n0g + seg);
        cp16(smb + PS_WL + (uint32_t)(row * 40 + seg) * 2, Wl_g + (size_t)row * 4096 + n0g + seg);
    }
    cp_commit(); cp_wait<0>();
    __syncthreads();

    __half (*WH)[40] = (__half (*)[40])(sm + PS_WH);
    __half (*WL)[40] = (__half (*)[40])(sm + PS_WL);

    const int m = tid & 127, grp = tid >> 7;
    const int pc = grp * 8;
    float cv[2];
    {
        float2 c2 = *(const float2*)(g_C + (size_t)m * UN + bx * 8 + grp * 2);
        cv[0] = c2.x; cv[1] = c2.y;
    }
    const int arow = tid >> 2, aseg = (tid & 3) * 8;

    for (int t = 0; t < TN; t++) {
        const __half* __restrict__ Hhi = g_Hhi + (size_t)t * (BSZ * UN);
        const __half* __restrict__ Hlo = g_Hlo + (size_t)t * (BSZ * UN);

        float zkf[8];
        {
            const float* zk = g_ZK + ((size_t)t * BSZ + m) * 4096 + n0g + pc;
            float4 v0 = *(const float4*)(zk);
            float4 v1 = *(const float4*)(zk + 4);
            zkf[0] = v0.x; zkf[1] = v0.y; zkf[2] = v0.z; zkf[3] = v0.w;
            zkf[4] = v1.x; zkf[5] = v1.y; zkf[6] = v1.z; zkf[7] = v1.w;
        }

        auto issueA = [&](int chunk) {
            int buf = chunk % 3;
            uint32_t ad = smb + PS_A + buf * PS_ABUF + (uint32_t)(arow * 40 + aseg) * 2;
            cp16(ad,         Hhi + (size_t)arow * 1024 + chunk * 32 + aseg);
            cp16(ad + 10240, Hlo + (size_t)arow * 1024 + chunk * 32 + aseg);
            cp_commit();
        };

        wmma::fragment<wmma::accumulator, 16, 16, 16, float> a0[2], a1[2], a2[2];
#pragma unroll
        for (int i = 0; i < 2; i++) {
            wmma::fill_fragment(a0[i], 0.f);
            wmma::fill_fragment(a1[i], 0.f);
            wmma::fill_fragment(a2[i], 0.f);
        }

        issueA(0); issueA(1);
        for (int c = 0; c < 32; c++) {
            if (c < 31) cp_wait<1>(); else cp_wait<0>();
            __syncthreads();
            if (c + 2 < 32) issueA(c + 2);

            int buf = c % 3;
            __half (*Ah)[40] = (__half (*)[40])(sm + PS_A + buf * PS_ABUF);
            __half (*Al)[40] = (__half (*)[40])(sm + PS_A + buf * PS_ABUF + 10240);

            const int kkg = c * 32 + g * 16;
            const int ka = g * 16;
            wmma::fragment<wmma::matrix_b, 16, 16, 16, __half, wmma::row_major> bh, bl;
            wmma::fragment<wmma::matrix_a, 16, 16, 16, __half, wmma::row_major> ah0, ah1, al0, al1;
            wmma::load_matrix_sync(bh, &WH[kkg][wn * 16], 40);
            wmma::load_matrix_sync(bl, &WL[kkg][wn * 16], 40);
            wmma::load_matrix_sync(ah0, &Ah[wm * 32][ka], 40);
            wmma::load_matrix_sync(ah1, &Ah[wm * 32 + 16][ka], 40);
            wmma::load_matrix_sync(al0, &Al[wm * 32][ka], 40);
            wmma::load_matrix_sync(al1, &Al[wm * 32 + 16][ka], 40);
            // 6 independent chains: a0 = Hhi*Whi ; a1 = Hhi*(Wlo*256) ; a2 = (Hlo*256)*Whi
            wmma::mma_sync(a0[0], ah0, bh, a0[0]);
            wmma::mma_sync(a0[1], ah1, bh, a0[1]);
            wmma::mma_sync(a1[0], ah0, bl, a1[0]);
            wmma::mma_sync(a1[1], ah1, bl, a1[1]);
            wmma::mma_sync(a2[0], al0, bh, a2[0]);
            wmma::mma_sync(a2[1], al1, bh, a2[1]);
        }

        // combine: z = a0 + (a1 + a2)/256 ; partial per group
        __syncthreads();
        float (*zp)[36] = (float (*)[36])(sm + PS_A + g * 18432);
#pragma unroll
        for (int i = 0; i < 2; i++) {
#pragma unroll
            for (int e = 0; e < a0[0].num_elements; e++)
                a0[i].x[e] += (a1[i].x[e] + a2[i].x[e]) * INV256;
            wmma::store_matrix_sync(&zp[wm * 32 + i * 16][wn * 16], a0[i], 36, wmma::mem_row_major);
        }
        __syncthreads();

        float (*z0)[36] = (float (*)[36])(sm + PS_A);
        float (*z1)[36] = (float (*)[36])(sm + PS_A + 18432);
        __half2 hh2, hl2;
#pragma unroll
        for (int e = 0; e < 2; e++) {
            float zi = z0[m][pc + e * 4 + 0] + z1[m][pc + e * 4 + 0] + zkf[e * 4 + 0];
            float zf = z0[m][pc + e * 4 + 1] + z1[m][pc + e * 4 + 1] + zkf[e * 4 + 1];
            float zg = z0[m][pc + e * 4 + 2] + z1[m][pc + e * 4 + 2] + zkf[e * 4 + 2];
            float zo = z0[m][pc + e * 4 + 3] + z1[m][pc + e * 4 + 3] + zkf[e * 4 + 3];
            float si = 1.f / (1.f + __expf(-zi));
            float sf = 1.f / (1.f + __expf(-zf));
            float so = 1.f / (1.f + __expf(-zo));
            float cn = sf * cv[e] + si * tanhf(zg);
            float hn = so * tanhf(cn);
            cv[e] = cn;
            __half h, l; hsplit(hn, h, l);
            if (e == 0) { hh2.x = h; hl2.x = l; } else { hh2.y = h; hl2.y = l; }
        }
        size_t ho = (size_t)(t + 1) * (BSZ * UN) + (size_t)m * UN + bx * 8 + grp * 2;
        *(__half2*)(g_Hhi + ho) = hh2;
        *(__half2*)(g_Hlo + ho) = hl2;

        __threadfence();
        __syncthreads();
        if (tid == 0) {
            atomicAdd(&g_count, 1);
            volatile int* gc = &g_count;
            int target = NCTA * (t + 1);
            while (*gc < target) __nanosleep(64);
        }
        __syncthreads();
    }
}

// ---------------- host ----------------
extern "C" void kernel_launch(void* const* d_in, const int* in_sizes, int n_in,
                              void* d_out, int out_size)
{
    const float* h0    = (const float*)d_in[0];
    const float* c0    = (const float*)d_in[1];
    const float* X     = (const float*)d_in[2];
    const float* W_emb = (const float*)d_in[3];
    const float* b_emb = (const float*)d_in[4];
    const float* W_k   = (const float*)d_in[5];
    const float* W_r   = (const float*)d_in[6];
    const float* b_r   = (const float*)d_in[7];
    const float* W_out = (const float*)d_in[8];
    const float* b_out = (const float*)d_in[9];
    (void)in_sizes; (void)n_in; (void)out_size;

    __half *pXh, *pEh, *pHhi, *pHlo;
    __half *pWembh, *pWembl, *pWouth, *pWoutl, *pWkh, *pWkl, *pWrh, *pWrl;
    float *pZK;
    cudaGetSymbolAddress((void**)&pXh, g_Xh);
    cudaGetSymbolAddress((void**)&pEh, g_Eh);
    cudaGetSymbolAddress((void**)&pHhi, g_Hhi);
    cudaGetSymbolAddress((void**)&pHlo, g_Hlo);
    cudaGetSymbolAddress((void**)&pWembh, g_Wemb_hi);
    cudaGetSymbolAddress((void**)&pWembl, g_Wemb_lo);
    cudaGetSymbolAddress((void**)&pWouth, g_Wout_hi);
    cudaGetSymbolAddress((void**)&pWoutl, g_Wout_lo);
    cudaGetSymbolAddress((void**)&pWkh, g_Wk_hi);
    cudaGetSymbolAddress((void**)&pWkl, g_Wk_lo);
    cudaGetSymbolAddress((void**)&pWrh, g_Wr_hi);
    cudaGetSymbolAddress((void**)&pWrl, g_Wr_lo);
    cudaGetSymbolAddress((void**)&pZK, g_ZK);

    cudaFuncSetAttribute(wgemm, cudaFuncAttributeMaxDynamicSharedMemorySize, WG_TOTAL);
    cudaFuncSetAttribute(lstm_persist4, cudaFuncAttributeMaxDynamicSharedMemorySize, PS_TOTAL);

    // 1. merged prep (also resets g_count each launch)
    prep_all<<<PREP_BLOCKS, 256>>>(X, h0, c0, W_emb, W_out, W_k, W_r);

    // 2. E = relu(X @ W_emb + b_emb) -> fp16
    {
        dim3 grid(1024 / 128, MROWS / 128);
        wgemm<<<grid, 256, WG_TOTAL>>>(pXh, pWembh, pWembl, b_emb,
                                       nullptr, pEh, 1024, 0);
    }
    // 3. ZK = E @ W_k + b_r (fp32, permuted cols)
    {
        dim3 grid(4096 / 128, MROWS / 128);
        wgemm<<<grid, 256, WG_TOTAL>>>(pEh, pWkh, pWkl, b_r,
                                       pZK, nullptr, 4096, 1);
    }

    // 4. recurrence: persistent, fp16 3-term, W in SMEM
    lstm_persist4<<<NCTA, 512, PS_TOTAL>>>(pWrh, pWrl);

    // 5. OUT = H @ W_out + b_out, scattered to [b][t][:]
    {
        dim3 grid(1024 / 128, MROWS / 128);
        wgemm<<<grid, 256, WG_TOTAL>>>(pHhi + (size_t)BSZ * UN, pWouth, pWoutl, b_out,
                                       (float*)d_out, nullptr, 1024, 2);
    }
}

// round 13
// speedup vs baseline: 2.4949x; 1.4935x over previous
#include <cuda_runtime.h>
#include <cuda_fp16.h>
#include <mma.h>
#include <cstdint>

using namespace nvcuda;

#define BSZ 128
#define TN  512
#define UN  1024
#define MROWS (TN * BSZ)   // 65536
#define NCTA 128
#define INV256 0.00390625f

// ---------------- scratch (static device globals) ----------------
__device__ __half g_Xh [(size_t)MROWS * UN];
__device__ __half g_Eh [(size_t)MROWS * UN];
__device__ float  g_ZK [(size_t)MROWS * 4 * UN];   // permuted cols p=u*4+g
__device__ float  g_C  [(size_t)BSZ * UN];
__device__ __half g_Hhi[(size_t)(TN + 1) * BSZ * UN];
__device__ __half g_Wemb_hi[(size_t)UN * UN];
__device__ __half g_Wemb_lo[(size_t)UN * UN];           // x256
__device__ __half g_Wout_hi[(size_t)UN * UN];
__device__ __half g_Wout_lo[(size_t)UN * UN];           // x256
__device__ __half g_Wk_hi[(size_t)UN * 4 * UN];         // permuted cols
__device__ __half g_Wk_lo[(size_t)UN * 4 * UN];         // x256
__device__ __half g_Wr_hi[(size_t)UN * 4 * UN];         // permuted cols
__device__ __half g_Wr_lo[(size_t)UN * 4 * UN];         // x256
__device__ int    g_count;

struct __align__(8) H4 { __half v[4]; };

__device__ __forceinline__ void hsplit(float v, __half& h, __half& l) {
    h = __float2half_rn(v);
    l = __float2half_rn((v - __half2float(h)) * 256.0f);
}

__device__ __forceinline__ void cp16(uint32_t dst, const void* src) {
    asm volatile("cp.async.cg.shared.global [%0], [%1], 16;" :: "r"(dst), "l"(src));
}
__device__ __forceinline__ void cp_commit() { asm volatile("cp.async.commit_group;"); }
template<int N> __device__ __forceinline__ void cp_wait() {
    asm volatile("cp.async.wait_group %0;" :: "n"(N));
}

// ---------------- merged prep kernel ----------------
#define PREP_ST0   65536
#define PREP_WE0   66048
#define PREP_WO0   67072
#define PREP_WK0   68096
#define PREP_WR0   72192
#define PREP_BLOCKS 76288

__global__ __launch_bounds__(256) void prep_all(
    const float* __restrict__ X, const float* __restrict__ h0, const float* __restrict__ c0,
    const float* __restrict__ W_emb, const float* __restrict__ W_out,
    const float* __restrict__ W_k, const float* __restrict__ W_r)
{
    const int b = blockIdx.x, tid = threadIdx.x;
    if (b < PREP_ST0) {                    // X -> fp16, 4 elems/thread
        size_t i = (size_t)b * 256 + tid;
        size_t e = i * 4;
        size_t r = e >> 10;
        int k = (int)(e & 1023);
        int bb = (int)(r & 127), t = (int)(r >> 7);
        float4 v = *(const float4*)(X + ((size_t)bb * 513 + (size_t)t) * 1024 + k);
        H4 h;
        h.v[0] = __float2half_rn(v.x); h.v[1] = __float2half_rn(v.y);
        h.v[2] = __float2half_rn(v.z); h.v[3] = __float2half_rn(v.w);
        *(H4*)(g_Xh + e) = h;
    } else if (b < PREP_WE0) {             // init_state
        int i = (b - PREP_ST0) * 256 + tid;
        if (b == PREP_ST0 && tid == 0) g_count = 0;
        g_C[i] = c0[i];
        g_Hhi[i] = __float2half_rn(h0[i]);
    } else if (b < PREP_WK0) {             // W_emb / W_out split (no perm), lo x256
        int isout = (b >= PREP_WO0);
        const float* W = isout ? W_out : W_emb;
        __half* hi = isout ? g_Wout_hi : g_Wemb_hi;
        __half* lo = isout ? g_Wout_lo : g_Wemb_lo;
        size_t q = (size_t)(b - (isout ? PREP_WO0 : PREP_WE0)) * 256 + tid;
        size_t e = q * 4;
        float4 v = *(const float4*)(W + e);
        H4 h, l;
        hsplit(v.x, h.v[0], l.v[0]); hsplit(v.y, h.v[1], l.v[1]);
        hsplit(v.z, h.v[2], l.v[2]); hsplit(v.w, h.v[3], l.v[3]);
        *(H4*)(hi + e) = h;
        *(H4*)(lo + e) = l;
    } else {                               // W_k / W_r permuted split, lo x256
        int isr = (b >= PREP_WR0);
        const float* W = isr ? W_r : W_k;
        __half* hi = isr ? g_Wr_hi : g_Wk_hi;
        __half* lo = isr ? g_Wr_lo : g_Wk_lo;
        size_t q = (size_t)(b - (isr ? PREP_WR0 : PREP_WK0)) * 256 + tid;
        int row = (int)(q >> 10);
        int qc = (int)(q & 1023);
        const float* src = W + (size_t)row * 4096 + qc;
        H4 h, l;
        hsplit(src[0],    h.v[0], l.v[0]);
        hsplit(src[1024], h.v[1], l.v[1]);
        hsplit(src[2048], h.v[2], l.v[2]);
        hsplit(src[3072], h.v[3], l.v[3]);
        size_t e = (size_t)row * 4096 + (size_t)qc * 4;
        *(H4*)(hi + e) = h;
        *(H4*)(lo + e) = l;
    }
}

// ---------------- fp16 2-term wmma GEMM, 2-buffer cp.async pipeline (unchanged) ----------------
#define WG_BUF   27648
#define WG_BIAS  55296
#define WG_TOTAL 63488

__global__ __launch_bounds__(256) void wgemm(
    const __half* __restrict__ A,
    const __half* __restrict__ Bhi, const __half* __restrict__ Blo,
    const float* __restrict__ bias, float* __restrict__ D,
    __half* __restrict__ Dh,
    int N, int mode)
{
    extern __shared__ char sm[];
    const uint32_t smb = (uint32_t)__cvta_generic_to_shared(sm);

    const int tid = threadIdx.x;
    const int n0 = blockIdx.x * 128, m0 = blockIdx.y * 128;
    const int wid = tid >> 5, lane = tid & 31;
    const int wm = wid & 3, wn = wid >> 2;

    float (*sbias)[128] = (float (*)[128])(sm + WG_BIAS);
    for (int i = tid; i < 2048; i += 256) {
        int col = i & 127;
        int p = n0 + col;
        float bv = (mode == 1) ? bias[(p & 3) * 1024 + (p >> 2)] : bias[p];
        sbias[i >> 7][col] = bv;
    }
    __syncthreads();

    wmma::fragment<wmma::accumulator, 16, 16, 16, float> acc[2][4];
#pragma unroll
    for (int i = 0; i < 2; i++)
#pragma unroll
        for (int j = 0; j < 4; j++)
            wmma::load_matrix_sync(acc[i][j], &sbias[0][wn * 64 + j * 16], 128, wmma::mem_row_major);
    __syncthreads();

    const int arow = tid >> 1, aseg = (tid & 1) * 16;
    const int brow = tid >> 3, bseg = (tid & 7) * 16;

    auto issue = [&](int c) {
        uint32_t base = smb + (uint32_t)(c & 1) * WG_BUF;
        int k0 = c * 32;
        uint32_t ad = base + (uint32_t)(arow * 40 + aseg) * 2;
        const __half* ap = A + (size_t)(m0 + arow) * 1024 + k0 + aseg;
        cp16(ad,      ap);
        cp16(ad + 16, ap + 8);
        uint32_t bd = base + 10240 + (uint32_t)(brow * 136 + bseg) * 2;
        const __half* bhp = Bhi + (size_t)(k0 + brow) * N + n0 + bseg;
        const __half* blp = Blo + (size_t)(k0 + brow) * N + n0 + bseg;
        cp16(bd,             bhp);
        cp16(bd + 16,        bhp + 8);
        cp16(bd + 8704,      blp);
        cp16(bd + 8704 + 16, blp + 8);
        cp_commit();
    };

    const __half hinv = __float2half_rn(INV256);

    issue(0);
    for (int c = 0; c < 32; c++) {
        cp_wait<0>();
        __syncthreads();
        if (c + 1 < 32) issue(c + 1);

        char* bufp = sm + (c & 1) * WG_BUF;
        __half (*sA)[40]    = (__half (*)[40])(bufp);
        __half (*sBhi)[136] = (__half (*)[136])(bufp + 10240);
        __half (*sBlo)[136] = (__half (*)[136])(bufp + 10240 + 8704);

#pragma unroll
        for (int kk = 0; kk < 32; kk += 16) {
            wmma::fragment<wmma::matrix_a, 16, 16, 16, __half, wmma::row_major> ah[2], ahs[2];
            wmma::fragment<wmma::matrix_b, 16, 16, 16, __half, wmma::row_major> bh[4], bl[4];
#pragma unroll
            for (int i = 0; i < 2; i++) {
                wmma::load_matrix_sync(ah[i], &sA[wm * 32 + i * 16][kk], 40);
#pragma unroll
                for (int e = 0; e < ah[i].num_elements; e++)
                    ahs[i].x[e] = __hmul(ah[i].x[e], hinv);
            }
#pragma unroll
            for (int j = 0; j < 4; j++) {
                wmma::load_matrix_sync(bh[j], &sBhi[kk][wn * 64 + j * 16], 136);
                wmma::load_matrix_sync(bl[j], &sBlo[kk][wn * 64 + j * 16], 136);
            }
#pragma unroll
            for (int i = 0; i < 2; i++)
#pragma unroll
                for (int j = 0; j < 4; j++) {
                    wmma::mma_sync(acc[i][j], ah[i],  bh[j], acc[i][j]);
                    wmma::mma_sync(acc[i][j], ahs[i], bl[j], acc[i][j]);
                }
        }
    }

    if (mode == 0) {
        float (*stage)[16] = (float (*)[16])((float*)(sm + WG_BIAS) + wid * 256);
        __syncthreads();
#pragma unroll
        for (int i = 0; i < 2; i++)
#pragma unroll
            for (int j = 0; j < 4; j++) {
                for (int e = 0; e < acc[i][j].num_elements; e++)
                    acc[i][j].x[e] = fmaxf(acc[i][j].x[e], 0.f);
                wmma::store_matrix_sync(&stage[0][0], acc[i][j], 16, wmma::mem_row_major);
                __syncwarp();
                int r = lane & 15, c8 = (lane >> 4) * 8;
                size_t row = (size_t)(m0 + wm * 32 + i * 16 + r);
                size_t off = row * 1024 + (n0 + wn * 64 + j * 16 + c8);
                H4 h0v, h1v;
#pragma unroll
                for (int e = 0; e < 4; e++) h0v.v[e] = __float2half_rn(stage[r][c8 + e]);
#pragma unroll
                for (int e = 0; e < 4; e++) h1v.v[e] = __float2half_rn(stage[r][c8 + 4 + e]);
                *(H4*)(Dh + off)     = h0v;
                *(H4*)(Dh + off + 4) = h1v;
                __syncwarp();
            }
        return;
    }

#pragma unroll
    for (int i = 0; i < 2; i++)
#pragma unroll
        for (int j = 0; j < 4; j++) {
            int col = n0 + wn * 64 + j * 16;
            if (mode == 2) {
                int t = m0 >> 7;
                int b = wm * 32 + i * 16;
                float* p = D + (size_t)t * 1024 + (size_t)b * ((size_t)TN * 1024) + col;
                wmma::store_matrix_sync(p, acc[i][j], (unsigned)(TN * 1024), wmma::mem_row_major);
            } else {
                int row = m0 + wm * 32 + i * 16;
                wmma::store_matrix_sync(D + (size_t)row * N + col, acc[i][j], N, wmma::mem_row_major);
            }
        }
}

// ---------------- persistent recurrence: fp16 2-term, K-chunk 64, W in SMEM ----------------
// 128 CTAs x 512 thr. SMEM: WH[1024][40] 80K | WL 80K | A: 3 bufs x 18432 (hi[128][72]).
// 16 warps: group g=wid>>3 takes k-half [g*32, g*32+32) of each 64-chunk.
// Warp tile M32 x N16, 4 indep acc chains (hh0, hh1, hl0, hl1).
#define PS_WH 0
#define PS_WL 81920
#define PS_A  163840
#define PS_ABUF 18432
#define PS_TOTAL (163840 + 3 * PS_ABUF)    // 219136

__global__ __launch_bounds__(512, 1) void lstm_persist5(
    const __half* __restrict__ Wh_g, const __half* __restrict__ Wl_g)
{
    extern __shared__ char sm[];
    const uint32_t smb = (uint32_t)__cvta_generic_to_shared(sm);
    const int tid = threadIdx.x, wid = tid >> 5;
    const int bx = blockIdx.x;
    const int n0g = bx * 32;
    const int g = wid >> 3, w8 = wid & 7;
    const int wm = w8 >> 1, wn = w8 & 1;

    for (int i = tid; i < 4096; i += 512) {
        int row = i >> 2, seg = (i & 3) * 8;
        cp16(smb + PS_WH + (uint32_t)(row * 40 + seg) * 2, Wh_g + (size_t)row * 4096 + n0g + seg);
        cp16(smb + PS_WL + (uint32_t)(row * 40 + seg) * 2, Wl_g + (size_t)row * 4096 + n0g + seg);
    }
    cp_commit(); cp_wait<0>();
    __syncthreads();

    __half (*WH)[40] = (__half (*)[40])(sm + PS_WH);
    __half (*WL)[40] = (__half (*)[40])(sm + PS_WL);

    const int m = tid & 127, grp = tid >> 7;
    const int pc = grp * 8;
    float cv[2];
    {
        float2 c2 = *(const float2*)(g_C + (size_t)m * UN + bx * 8 + grp * 2);
        cv[0] = c2.x; cv[1] = c2.y;
    }
    // A cp.async: chunk = 128 rows x 64 cols fp16 = 16KB; 512 thr x 2 cp16
    const int arow = tid >> 2, aseg = (tid & 3) * 16;

    for (int t = 0; t < TN; t++) {
        const __half* __restrict__ Hhi = g_Hhi + (size_t)t * (BSZ * UN);

        float zkf[8];
        {
            const float* zk = g_ZK + ((size_t)t * BSZ + m) * 4096 + n0g + pc;
            float4 v0 = *(const float4*)(zk);
            float4 v1 = *(const float4*)(zk + 4);
            zkf[0] = v0.x; zkf[1] = v0.y; zkf[2] = v0.z; zkf[3] = v0.w;
            zkf[4] = v1.x; zkf[5] = v1.y; zkf[6] = v1.z; zkf[7] = v1.w;
        }

        auto issueA = [&](int chunk) {
            int buf = chunk % 3;
            uint32_t ad = smb + PS_A + buf * PS_ABUF + (uint32_t)(arow * 72 + aseg) * 2;
            const __half* src = Hhi + (size_t)arow * 1024 + chunk * 64 + aseg;
            cp16(ad,      src);
            cp16(ad + 16, src + 8);
            cp_commit();
        };

        // 4 independent accumulator chains: a0[i] = Hhi x Whi ; a1[i] = Hhi x (Wlo*256)
        wmma::fragment<wmma::accumulator, 16, 16, 16, float> a0[2], a1[2];
#pragma unroll
        for (int i = 0; i < 2; i++) {
            wmma::fill_fragment(a0[i], 0.f);
            wmma::fill_fragment(a1[i], 0.f);
        }

        issueA(0); issueA(1);
        for (int c = 0; c < 16; c++) {
            if (c < 15) cp_wait<1>(); else cp_wait<0>();
            __syncthreads();
            if (c + 2 < 16) issueA(c + 2);

            int buf = c % 3;
            __half (*Ah)[72] = (__half (*)[72])(sm + PS_A + buf * PS_ABUF);

#pragma unroll
            for (int s = 0; s < 2; s++) {
                const int kkg = c * 64 + g * 32 + s * 16;   // W row
                const int ka  = g * 32 + s * 16;            // A col
                wmma::fragment<wmma::matrix_b, 16, 16, 16, __half, wmma::row_major> bh, bl;
                wmma::fragment<wmma::matrix_a, 16, 16, 16, __half, wmma::row_major> ah0, ah1;
                wmma::load_matrix_sync(bh, &WH[kkg][wn * 16], 40);
                wmma::load_matrix_sync(bl, &WL[kkg][wn * 16], 40);
                wmma::load_matrix_sync(ah0, &Ah[wm * 32][ka], 72);
                wmma::load_matrix_sync(ah1, &Ah[wm * 32 + 16][ka], 72);
                wmma::mma_sync(a0[0], ah0, bh, a0[0]);
                wmma::mma_sync(a0[1], ah1, bh, a0[1]);
                wmma::mma_sync(a1[0], ah0, bl, a1[0]);
                wmma::mma_sync(a1[1], ah1, bl, a1[1]);
            }
        }

        // combine: z = a0 + a1/256 ; partial per group
        __syncthreads();
        float (*zp)[36] = (float (*)[36])(sm + PS_A + g * 18432);
#pragma unroll
        for (int i = 0; i < 2; i++) {
#pragma unroll
            for (int e = 0; e < a0[0].num_elements; e++)
                a0[i].x[e] += a1[i].x[e] * INV256;
            wmma::store_matrix_sync(&zp[wm * 32 + i * 16][wn * 16], a0[i], 36, wmma::mem_row_major);
        }
        __syncthreads();

        float (*z0)[36] = (float (*)[36])(sm + PS_A);
        float (*z1)[36] = (float (*)[36])(sm + PS_A + 18432);
        __half2 hh2;
#pragma unroll
        for (int e = 0; e < 2; e++) {
            float zi = z0[m][pc + e * 4 + 0] + z1[m][pc + e * 4 + 0] + zkf[e * 4 + 0];
            float zf = z0[m][pc + e * 4 + 1] + z1[m][pc + e * 4 + 1] + zkf[e * 4 + 1];
            float zg = z0[m][pc + e * 4 + 2] + z1[m][pc + e * 4 + 2] + zkf[e * 4 + 2];
            float zo = z0[m][pc + e * 4 + 3] + z1[m][pc + e * 4 + 3] + zkf[e * 4 + 3];
            float si = 1.f / (1.f + __expf(-zi));
            float sf = 1.f / (1.f + __expf(-zf));
            float so = 1.f / (1.f + __expf(-zo));
            float cn = sf * cv[e] + si * tanhf(zg);
            float hn = so * tanhf(cn);
            cv[e] = cn;
            __half h = __float2half_rn(hn);
            if (e == 0) hh2.x = h; else hh2.y = h;
        }
        size_t ho = (size_t)(t + 1) * (BSZ * UN) + (size_t)m * UN + bx * 8 + grp * 2;
        *(__half2*)(g_Hhi + ho) = hh2;

        __threadfence();
        __syncthreads();
        if (tid == 0) {
            atomicAdd(&g_count, 1);
            volatile int* gc = &g_count;
            int target = NCTA * (t + 1);
            while (*gc < target) __nanosleep(64);
        }
        __syncthreads();
    }
}

// ---------------- host ----------------
extern "C" void kernel_launch(void* const* d_in, const int* in_sizes, int n_in,
                              void* d_out, int out_size)
{
    const float* h0    = (const float*)d_in[0];
    const float* c0    = (const float*)d_in[1];
    const float* X     = (const float*)d_in[2];
    const float* W_emb = (const float*)d_in[3];
    const float* b_emb = (const float*)d_in[4];
    const float* W_k   = (const float*)d_in[5];
    const float* W_r   = (const float*)d_in[6];
    const float* b_r   = (const float*)d_in[7];
    const float* W_out = (const float*)d_in[8];
    const float* b_out = (const float*)d_in[9];
    (void)in_sizes; (void)n_in; (void)out_size;

    __half *pXh, *pEh, *pHhi;
    __half *pWembh, *pWembl, *pWouth, *pWoutl, *pWkh, *pWkl, *pWrh, *pWrl;
    float *pZK;
    cudaGetSymbolAddress((void**)&pXh, g_Xh);
    cudaGetSymbolAddress((void**)&pEh, g_Eh);
    cudaGetSymbolAddress((void**)&pHhi, g_Hhi);
    cudaGetSymbolAddress((void**)&pWembh, g_Wemb_hi);
    cudaGetSymbolAddress((void**)&pWembl, g_Wemb_lo);
    cudaGetSymbolAddress((void**)&pWouth, g_Wout_hi);
    cudaGetSymbolAddress((void**)&pWoutl, g_Wout_lo);
    cudaGetSymbolAddress((void**)&pWkh, g_Wk_hi);
    cudaGetSymbolAddress((void**)&pWkl, g_Wk_lo);
    cudaGetSymbolAddress((void**)&pWrh, g_Wr_hi);
    cudaGetSymbolAddress((void**)&pWrl, g_Wr_lo);
    cudaGetSymbolAddress((void**)&pZK, g_ZK);

    cudaFuncSetAttribute(wgemm, cudaFuncAttributeMaxDynamicSharedMemorySize, WG_TOTAL);
    cudaFuncSetAttribute(lstm_persist5, cudaFuncAttributeMaxDynamicSharedMemorySize, PS_TOTAL);

    // 1. merged prep (also resets g_count each replay)
    prep_all<<<PREP_BLOCKS, 256>>>(X, h0, c0, W_emb, W_out, W_k, W_r);

    // 2. E = relu(X @ W_emb + b_emb) -> fp16
    {
        dim3 grid(1024 / 128, MROWS / 128);
        wgemm<<<grid, 256, WG_TOTAL>>>(pXh, pWembh, pWembl, b_emb,
                                       nullptr, pEh, 1024, 0);
    }
    // 3. ZK = E @ W_k + b_r (fp32, permuted cols)
    {
        dim3 grid(4096 / 128, MROWS / 128);
        wgemm<<<grid, 256, WG_TOTAL>>>(pEh, pWkh, pWkl, b_r,
                                       pZK, nullptr, 4096, 1);
    }

    // 4. recurrence: persistent, fp16 2-term, chunk-64, W in SMEM
    lstm_persist5<<<NCTA, 512, PS_TOTAL>>>(pWrh, pWrl);

    // 5. OUT = H @ W_out + b_out, scattered to [b][t][:]
    {
        dim3 grid(1024 / 128, MROWS / 128);
        wgemm<<<grid, 256, WG_TOTAL>>>(pHhi + (size_t)BSZ * UN, pWouth, pWoutl, b_out,
                                       (float*)d_out, nullptr, 1024, 2);
    }
}

// round 14
// speedup vs baseline: 3.1576x; 1.2656x over previous
#include <cuda_runtime.h>
#include <cuda_fp16.h>
#include <mma.h>
#include <cstdint>

using namespace nvcuda;

#define BSZ 128
#define TN  512
#define UN  1024
#define MROWS (TN * BSZ)   // 65536
#define NCTA 128
#define INV256 0.00390625f

// ---------------- scratch (static device globals) ----------------
__device__ __half g_Xh [(size_t)MROWS * UN];
__device__ __half g_Eh [(size_t)MROWS * UN];
__device__ float  g_ZK [(size_t)MROWS * 4 * UN];   // permuted cols p=u*4+g
__device__ float  g_C  [(size_t)BSZ * UN];
__device__ __half g_Hhi[(size_t)(TN + 1) * BSZ * UN];
__device__ __half g_Wemb[(size_t)UN * UN];
__device__ __half g_Wout[(size_t)UN * UN];
__device__ __half g_Wk  [(size_t)UN * 4 * UN];          // permuted cols
__device__ __half g_Wr_hi[(size_t)UN * 4 * UN];         // permuted cols
__device__ __half g_Wr_lo[(size_t)UN * 4 * UN];         // x256
__device__ int    g_count;

struct __align__(8) H4 { __half v[4]; };

__device__ __forceinline__ void hsplit(float v, __half& h, __half& l) {
    h = __float2half_rn(v);
    l = __float2half_rn((v - __half2float(h)) * 256.0f);
}

__device__ __forceinline__ void cp16(uint32_t dst, const void* src) {
    asm volatile("cp.async.cg.shared.global [%0], [%1], 16;" :: "r"(dst), "l"(src));
}
__device__ __forceinline__ void cp_commit() { asm volatile("cp.async.commit_group;"); }
template<int N> __device__ __forceinline__ void cp_wait() {
    asm volatile("cp.async.wait_group %0;" :: "n"(N));
}

// ---------------- merged prep kernel ----------------
// [0,65536) X->fp16 | [65536,66048) init_state | [66048,67072) W_emb fp16 |
// [67072,68096) W_out fp16 | [68096,72192) W_k perm fp16 | [72192,76288) W_r perm split
#define PREP_ST0   65536
#define PREP_WE0   66048
#define PREP_WO0   67072
#define PREP_WK0   68096
#define PREP_WR0   72192
#define PREP_BLOCKS 76288

__global__ __launch_bounds__(256) void prep_all(
    const float* __restrict__ X, const float* __restrict__ h0, const float* __restrict__ c0,
    const float* __restrict__ W_emb, const float* __restrict__ W_out,
    const float* __restrict__ W_k, const float* __restrict__ W_r)
{
    const int b = blockIdx.x, tid = threadIdx.x;
    if (b < PREP_ST0) {                    // X -> fp16, 4 elems/thread
        size_t i = (size_t)b * 256 + tid;
        size_t e = i * 4;
        size_t r = e >> 10;
        int k = (int)(e & 1023);
        int bb = (int)(r & 127), t = (int)(r >> 7);
        float4 v = *(const float4*)(X + ((size_t)bb * 513 + (size_t)t) * 1024 + k);
        H4 h;
        h.v[0] = __float2half_rn(v.x); h.v[1] = __float2half_rn(v.y);
        h.v[2] = __float2half_rn(v.z); h.v[3] = __float2half_rn(v.w);
        *(H4*)(g_Xh + e) = h;
    } else if (b < PREP_WE0) {             // init_state
        int i = (b - PREP_ST0) * 256 + tid;
        if (b == PREP_ST0 && tid == 0) g_count = 0;
        g_C[i] = c0[i];
        g_Hhi[i] = __float2half_rn(h0[i]);
    } else if (b < PREP_WK0) {             // W_emb / W_out -> fp16 (no perm, no split)
        int isout = (b >= PREP_WO0);
        const float* W = isout ? W_out : W_emb;
        __half* dst = isout ? g_Wout : g_Wemb;
        size_t q = (size_t)(b - (isout ? PREP_WO0 : PREP_WE0)) * 256 + tid;
        size_t e = q * 4;
        float4 v = *(const float4*)(W + e);
        H4 h;
        h.v[0] = __float2half_rn(v.x); h.v[1] = __float2half_rn(v.y);
        h.v[2] = __float2half_rn(v.z); h.v[3] = __float2half_rn(v.w);
        *(H4*)(dst + e) = h;
    } else if (b < PREP_WR0) {             // W_k permuted -> fp16 (no split)
        size_t q = (size_t)(b - PREP_WK0) * 256 + tid;
        int row = (int)(q >> 10);
        int qc = (int)(q & 1023);
        const float* src = W_k + (size_t)row * 4096 + qc;
        H4 h;
        h.v[0] = __float2half_rn(src[0]);
        h.v[1] = __float2half_rn(src[1024]);
        h.v[2] = __float2half_rn(src[2048]);
        h.v[3] = __float2half_rn(src[3072]);
        *(H4*)(g_Wk + (size_t)row * 4096 + (size_t)qc * 4) = h;
    } else {                               // W_r permuted split, lo x256
        size_t q = (size_t)(b - PREP_WR0) * 256 + tid;
        int row = (int)(q >> 10);
        int qc = (int)(q & 1023);
        const float* src = W_r + (size_t)row * 4096 + qc;
        H4 h, l;
        hsplit(src[0],    h.v[0], l.v[0]);
        hsplit(src[1024], h.v[1], l.v[1]);
        hsplit(src[2048], h.v[2], l.v[2]);
        hsplit(src[3072], h.v[3], l.v[3]);
        size_t e = (size_t)row * 4096 + (size_t)qc * 4;
        *(H4*)(g_Wr_hi + e) = h;
        *(H4*)(g_Wr_lo + e) = l;
    }
}

// ---------------- fp16 1-term wmma GEMM, 2-buffer cp.async pipeline ----------------
// D = A(fp16) @ B(fp16) + bias
// mode 0: relu, write fp16 D (g_Eh). mode 1: fp32 D, perm bias. mode 2: d_out scatter.
// smem per buf (18944B): A[128][40] 10240 | B[32][136] 8704
#define WG_BUF   18944
#define WG_BIAS  37888
#define WG_TOTAL 46080

__global__ __launch_bounds__(256) void wgemm(
    const __half* __restrict__ A, const __half* __restrict__ B,
    const float* __restrict__ bias, float* __restrict__ D,
    __half* __restrict__ Dh,
    int N, int mode)
{
    extern __shared__ char sm[];
    const uint32_t smb = (uint32_t)__cvta_generic_to_shared(sm);

    const int tid = threadIdx.x;
    const int n0 = blockIdx.x * 128, m0 = blockIdx.y * 128;
    const int wid = tid >> 5, lane = tid & 31;
    const int wm = wid & 3, wn = wid >> 2;

    float (*sbias)[128] = (float (*)[128])(sm + WG_BIAS);
    for (int i = tid; i < 2048; i += 256) {
        int col = i & 127;
        int p = n0 + col;
        float bv = (mode == 1) ? bias[(p & 3) * 1024 + (p >> 2)] : bias[p];
        sbias[i >> 7][col] = bv;
    }
    __syncthreads();

    wmma::fragment<wmma::accumulator, 16, 16, 16, float> acc[2][4];
#pragma unroll
    for (int i = 0; i < 2; i++)
#pragma unroll
        for (int j = 0; j < 4; j++)
            wmma::load_matrix_sync(acc[i][j], &sbias[0][wn * 64 + j * 16], 128, wmma::mem_row_major);
    __syncthreads();

    const int arow = tid >> 1, aseg = (tid & 1) * 16;
    const int brow = tid >> 3, bseg = (tid & 7) * 16;

    auto issue = [&](int c) {
        uint32_t base = smb + (uint32_t)(c & 1) * WG_BUF;
        int k0 = c * 32;
        uint32_t ad = base + (uint32_t)(arow * 40 + aseg) * 2;
        const __half* ap = A + (size_t)(m0 + arow) * 1024 + k0 + aseg;
        cp16(ad,      ap);
        cp16(ad + 16, ap + 8);
        uint32_t bd = base + 10240 + (uint32_t)(brow * 136 + bseg) * 2;
        const __half* bp = B + (size_t)(k0 + brow) * N + n0 + bseg;
        cp16(bd,      bp);
        cp16(bd + 16, bp + 8);
        cp_commit();
    };

    issue(0);
    for (int c = 0; c < 32; c++) {
        cp_wait<0>();
        __syncthreads();
        if (c + 1 < 32) issue(c + 1);

        char* bufp = sm + (c & 1) * WG_BUF;
        __half (*sA)[40]  = (__half (*)[40])(bufp);
        __half (*sB)[136] = (__half (*)[136])(bufp + 10240);

#pragma unroll
        for (int kk = 0; kk < 32; kk += 16) {
            wmma::fragment<wmma::matrix_a, 16, 16, 16, __half, wmma::row_major> ah[2];
            wmma::fragment<wmma::matrix_b, 16, 16, 16, __half, wmma::row_major> bh[4];
#pragma unroll
            for (int i = 0; i < 2; i++)
                wmma::load_matrix_sync(ah[i], &sA[wm * 32 + i * 16][kk], 40);
#pragma unroll
            for (int j = 0; j < 4; j++)
                wmma::load_matrix_sync(bh[j], &sB[kk][wn * 64 + j * 16], 136);
#pragma unroll
            for (int i = 0; i < 2; i++)
#pragma unroll
                for (int j = 0; j < 4; j++)
                    wmma::mma_sync(acc[i][j], ah[i], bh[j], acc[i][j]);
        }
    }

    if (mode == 0) {
        float (*stage)[16] = (float (*)[16])((float*)(sm + WG_BIAS) + wid * 256);
        __syncthreads();
#pragma unroll
        for (int i = 0; i < 2; i++)
#pragma unroll
            for (int j = 0; j < 4; j++) {
                for (int e = 0; e < acc[i][j].num_elements; e++)
                    acc[i][j].x[e] = fmaxf(acc[i][j].x[e], 0.f);
                wmma::store_matrix_sync(&stage[0][0], acc[i][j], 16, wmma::mem_row_major);
                __syncwarp();
                int r = lane & 15, c8 = (lane >> 4) * 8;
                size_t row = (size_t)(m0 + wm * 32 + i * 16 + r);
                size_t off = row * 1024 + (n0 + wn * 64 + j * 16 + c8);
                H4 h0v, h1v;
#pragma unroll
                for (int e = 0; e < 4; e++) h0v.v[e] = __float2half_rn(stage[r][c8 + e]);
#pragma unroll
                for (int e = 0; e < 4; e++) h1v.v[e] = __float2half_rn(stage[r][c8 + 4 + e]);
                *(H4*)(Dh + off)     = h0v;
                *(H4*)(Dh + off + 4) = h1v;
                __syncwarp();
            }
        return;
    }

#pragma unroll
    for (int i = 0; i < 2; i++)
#pragma unroll
        for (int j = 0; j < 4; j++) {
            int col = n0 + wn * 64 + j * 16;
            if (mode == 2) {
                int t = m0 >> 7;
                int b = wm * 32 + i * 16;
                float* p = D + (size_t)t * 1024 + (size_t)b * ((size_t)TN * 1024) + col;
                wmma::store_matrix_sync(p, acc[i][j], (unsigned)(TN * 1024), wmma::mem_row_major);
            } else {
                int row = m0 + wm * 32 + i * 16;
                wmma::store_matrix_sync(D + (size_t)row * N + col, acc[i][j], N, wmma::mem_row_major);
            }
        }
}

// ---------------- persistent recurrence: fp16 2-term, K-chunk 64, W in SMEM (unchanged) ----------------
#define PS_WH 0
#define PS_WL 81920
#define PS_A  163840
#define PS_ABUF 18432
#define PS_TOTAL (163840 + 3 * PS_ABUF)    // 219136

__global__ __launch_bounds__(512, 1) void lstm_persist5(
    const __half* __restrict__ Wh_g, const __half* __restrict__ Wl_g)
{
    extern __shared__ char sm[];
    const uint32_t smb = (uint32_t)__cvta_generic_to_shared(sm);
    const int tid = threadIdx.x, wid = tid >> 5;
    const int bx = blockIdx.x;
    const int n0g = bx * 32;
    const int g = wid >> 3, w8 = wid & 7;
    const int wm = w8 >> 1, wn = w8 & 1;

    for (int i = tid; i < 4096; i += 512) {
        int row = i >> 2, seg = (i & 3) * 8;
        cp16(smb + PS_WH + (uint32_t)(row * 40 + seg) * 2, Wh_g + (size_t)row * 4096 + n0g + seg);
        cp16(smb + PS_WL + (uint32_t)(row * 40 + seg) * 2, Wl_g + (size_t)row * 4096 + n0g + seg);
    }
    cp_commit(); cp_wait<0>();
    __syncthreads();

    __half (*WH)[40] = (__half (*)[40])(sm + PS_WH);
    __half (*WL)[40] = (__half (*)[40])(sm + PS_WL);

    const int m = tid & 127, grp = tid >> 7;
    const int pc = grp * 8;
    float cv[2];
    {
        float2 c2 = *(const float2*)(g_C + (size_t)m * UN + bx * 8 + grp * 2);
        cv[0] = c2.x; cv[1] = c2.y;
    }
    const int arow = tid >> 2, aseg = (tid & 3) * 16;

    for (int t = 0; t < TN; t++) {
        const __half* __restrict__ Hhi = g_Hhi + (size_t)t * (BSZ * UN);

        float zkf[8];
        {
            const float* zk = g_ZK + ((size_t)t * BSZ + m) * 4096 + n0g + pc;
            float4 v0 = *(const float4*)(zk);
            float4 v1 = *(const float4*)(zk + 4);
            zkf[0] = v0.x; zkf[1] = v0.y; zkf[2] = v0.z; zkf[3] = v0.w;
            zkf[4] = v1.x; zkf[5] = v1.y; zkf[6] = v1.z; zkf[7] = v1.w;
        }

        auto issueA = [&](int chunk) {
            int buf = chunk % 3;
            uint32_t ad = smb + PS_A + buf * PS_ABUF + (uint32_t)(arow * 72 + aseg) * 2;
            const __half* src = Hhi + (size_t)arow * 1024 + chunk * 64 + aseg;
            cp16(ad,      src);
            cp16(ad + 16, src + 8);
            cp_commit();
        };

        wmma::fragment<wmma::accumulator, 16, 16, 16, float> a0[2], a1[2];
#pragma unroll
        for (int i = 0; i < 2; i++) {
            wmma::fill_fragment(a0[i], 0.f);
            wmma::fill_fragment(a1[i], 0.f);
        }

        issueA(0); issueA(1);
        for (int c = 0; c < 16; c++) {
            if (c < 15) cp_wait<1>(); else cp_wait<0>();
            __syncthreads();
            if (c + 2 < 16) issueA(c + 2);

            int buf = c % 3;
            __half (*Ah)[72] = (__half (*)[72])(sm + PS_A + buf * PS_ABUF);

#pragma unroll
            for (int s = 0; s < 2; s++) {
                const int kkg = c * 64 + g * 32 + s * 16;
                const int ka  = g * 32 + s * 16;
                wmma::fragment<wmma::matrix_b, 16, 16, 16, __half, wmma::row_major> bh, bl;
                wmma::fragment<wmma::matrix_a, 16, 16, 16, __half, wmma::row_major> ah0, ah1;
                wmma::load_matrix_sync(bh, &WH[kkg][wn * 16], 40);
                wmma::load_matrix_sync(bl, &WL[kkg][wn * 16], 40);
                wmma::load_matrix_sync(ah0, &Ah[wm * 32][ka], 72);
                wmma::load_matrix_sync(ah1, &Ah[wm * 32 + 16][ka], 72);
                wmma::mma_sync(a0[0], ah0, bh, a0[0]);
                wmma::mma_sync(a0[1], ah1, bh, a0[1]);
                wmma::mma_sync(a1[0], ah0, bl, a1[0]);
                wmma::mma_sync(a1[1], ah1, bl, a1[1]);
            }
        }

        __syncthreads();
        float (*zp)[36] = (float (*)[36])(sm + PS_A + g * 18432);
#pragma unroll
        for (int i = 0; i < 2; i++) {
#pragma unroll
            for (int e = 0; e < a0[0].num_elements; e++)
                a0[i].x[e] += a1[i].x[e] * INV256;
            wmma::store_matrix_sync(&zp[wm * 32 + i * 16][wn * 16], a0[i], 36, wmma::mem_row_major);
        }
        __syncthreads();

        float (*z0)[36] = (float (*)[36])(sm + PS_A);
        float (*z1)[36] = (float (*)[36])(sm + PS_A + 18432);
        __half2 hh2;
#pragma unroll
        for (int e = 0; e < 2; e++) {
            float zi = z0[m][pc + e * 4 + 0] + z1[m][pc + e * 4 + 0] + zkf[e * 4 + 0];
            float zf = z0[m][pc + e * 4 + 1] + z1[m][pc + e * 4 + 1] + zkf[e * 4 + 1];
            float zg = z0[m][pc + e * 4 + 2] + z1[m][pc + e * 4 + 2] + zkf[e * 4 + 2];
            float zo = z0[m][pc + e * 4 + 3] + z1[m][pc + e * 4 + 3] + zkf[e * 4 + 3];
            float si = 1.f / (1.f + __expf(-zi));
            float sf = 1.f / (1.f + __expf(-zf));
            float so = 1.f / (1.f + __expf(-zo));
            float cn = sf * cv[e] + si * tanhf(zg);
            float hn = so * tanhf(cn);
            cv[e] = cn;
            __half h = __float2half_rn(hn);
            if (e == 0) hh2.x = h; else hh2.y = h;
        }
        size_t ho = (size_t)(t + 1) * (BSZ * UN) + (size_t)m * UN + bx * 8 + grp * 2;
        *(__half2*)(g_Hhi + ho) = hh2;

        __threadfence();
        __syncthreads();
        if (tid == 0) {
            atomicAdd(&g_count, 1);
            volatile int* gc = &g_count;
            int target = NCTA * (t + 1);
            while (*gc < target) __nanosleep(64);
        }
        __syncthreads();
    }
}

// ---------------- host ----------------
extern "C" void kernel_launch(void* const* d_in, const int* in_sizes, int n_in,
                              void* d_out, int out_size)
{
    const float* h0    = (const float*)d_in[0];
    const float* c0    = (const float*)d_in[1];
    const float* X     = (const float*)d_in[2];
    const float* W_emb = (const float*)d_in[3];
    const float* b_emb = (const float*)d_in[4];
    const float* W_k   = (const float*)d_in[5];
    const float* W_r   = (const float*)d_in[6];
    const float* b_r   = (const float*)d_in[7];
    const float* W_out = (const float*)d_in[8];
    const float* b_out = (const float*)d_in[9];
    (void)in_sizes; (void)n_in; (void)out_size;

    __half *pXh, *pEh, *pHhi, *pWemb, *pWout, *pWk, *pWrh, *pWrl;
    float *pZK;
    cudaGetSymbolAddress((void**)&pXh, g_Xh);
    cudaGetSymbolAddress((void**)&pEh, g_Eh);
    cudaGetSymbolAddress((void**)&pHhi, g_Hhi);
    cudaGetSymbolAddress((void**)&pWemb, g_Wemb);
    cudaGetSymbolAddress((void**)&pWout, g_Wout);
    cudaGetSymbolAddress((void**)&pWk, g_Wk);
    cudaGetSymbolAddress((void**)&pWrh, g_Wr_hi);
    cudaGetSymbolAddress((void**)&pWrl, g_Wr_lo);
    cudaGetSymbolAddress((void**)&pZK, g_ZK);

    cudaFuncSetAttribute(wgemm, cudaFuncAttributeMaxDynamicSharedMemorySize, WG_TOTAL);
    cudaFuncSetAttribute(lstm_persist5, cudaFuncAttributeMaxDynamicSharedMemorySize, PS_TOTAL);

    // 1. merged prep (also resets g_count each replay)
    prep_all<<<PREP_BLOCKS, 256>>>(X, h0, c0, W_emb, W_out, W_k, W_r);

    // 2. E = relu(X @ W_emb + b_emb) -> fp16
    {
        dim3 grid(1024 / 128, MROWS / 128);
        wgemm<<<grid, 256, WG_TOTAL>>>(pXh, pWemb, b_emb, nullptr, pEh, 1024, 0);
    }
    // 3. ZK = E @ W_k + b_r (fp32, permuted cols)
    {
        dim3 grid(4096 / 128, MROWS / 128);
        wgemm<<<grid, 256, WG_TOTAL>>>(pEh, pWk, b_r, pZK, nullptr, 4096, 1);
    }

    // 4. recurrence: persistent, fp16 2-term, chunk-64, W in SMEM
    lstm_persist5<<<NCTA, 512, PS_TOTAL>>>(pWrh, pWrl);

    // 5. OUT = H @ W_out + b_out, scattered to [b][t][:]
    {
        dim3 grid(1024 / 128, MROWS / 128);
        wgemm<<<grid, 256, WG_TOTAL>>>(pHhi + (size_t)BSZ * UN, pWout, b_out,
                                       (float*)d_out, nullptr, 1024, 2);
    }
}

// round 15
// speedup vs baseline: 3.4808x; 1.1024x over previous
#include <cuda_runtime.h>
#include <cuda_fp16.h>
#include <mma.h>
#include <cstdint>

using namespace nvcuda;

#define BSZ 128
#define TN  512
#define UN  1024
#define MROWS (TN * BSZ)   // 65536
#define NCTA 128

// ---------------- scratch (static device globals) ----------------
__device__ __half g_Xh [(size_t)MROWS * UN];
__device__ __half g_Eh [(size_t)MROWS * UN];
__device__ float  g_ZK [(size_t)MROWS * 4 * UN];   // permuted cols p=u*4+g
__device__ float  g_C  [(size_t)BSZ * UN];
__device__ __half g_Hhi[(size_t)(TN + 1) * BSZ * UN];
__device__ __half g_Wemb[(size_t)UN * UN];
__device__ __half g_Wout[(size_t)UN * UN];
__device__ __half g_Wk  [(size_t)UN * 4 * UN];     // permuted cols
__device__ __half g_Wr  [(size_t)UN * 4 * UN];     // permuted cols
__device__ int    g_count;

struct __align__(8) H4 { __half v[4]; };

__device__ __forceinline__ void cp16(uint32_t dst, const void* src) {
    asm volatile("cp.async.cg.shared.global [%0], [%1], 16;" :: "r"(dst), "l"(src));
}
__device__ __forceinline__ void cp_commit() { asm volatile("cp.async.commit_group;"); }
template<int N> __device__ __forceinline__ void cp_wait() {
    asm volatile("cp.async.wait_group %0;" :: "n"(N));
}

// ---------------- merged prep kernel ----------------
// [0,16384) X->fp16 (16 elems/thread) | [16384,16896) init_state |
// [16896,17920) W_emb | [17920,18944) W_out | [18944,23040) W_k perm | [23040,27136) W_r perm
#define PREP_ST0   16384
#define PREP_WE0   16896
#define PREP_WO0   17920
#define PREP_WK0   18944
#define PREP_WR0   23040
#define PREP_BLOCKS 27136

__global__ __launch_bounds__(256) void prep_all(
    const float* __restrict__ X, const float* __restrict__ h0, const float* __restrict__ c0,
    const float* __restrict__ W_emb, const float* __restrict__ W_out,
    const float* __restrict__ W_k, const float* __restrict__ W_r)
{
    const int b = blockIdx.x, tid = threadIdx.x;
    if (b < PREP_ST0) {                    // X -> fp16, 16 elems/thread (4x float4 MLP)
        size_t e = ((size_t)b * 256 + tid) * 16;
        size_t r = e >> 10;
        int k = (int)(e & 1023);
        int bb = (int)(r & 127), t = (int)(r >> 7);
        const float* src = X + ((size_t)bb * 513 + (size_t)t) * 1024 + k;
        float4 v0 = *(const float4*)(src);
        float4 v1 = *(const float4*)(src + 4);
        float4 v2 = *(const float4*)(src + 8);
        float4 v3 = *(const float4*)(src + 12);
        H4 h[4];
        h[0].v[0] = __float2half_rn(v0.x); h[0].v[1] = __float2half_rn(v0.y);
        h[0].v[2] = __float2half_rn(v0.z); h[0].v[3] = __float2half_rn(v0.w);
        h[1].v[0] = __float2half_rn(v1.x); h[1].v[1] = __float2half_rn(v1.y);
        h[1].v[2] = __float2half_rn(v1.z); h[1].v[3] = __float2half_rn(v1.w);
        h[2].v[0] = __float2half_rn(v2.x); h[2].v[1] = __float2half_rn(v2.y);
        h[2].v[2] = __float2half_rn(v2.z); h[2].v[3] = __float2half_rn(v2.w);
        h[3].v[0] = __float2half_rn(v3.x); h[3].v[1] = __float2half_rn(v3.y);
        h[3].v[2] = __float2half_rn(v3.z); h[3].v[3] = __float2half_rn(v3.w);
        *(int4*)(g_Xh + e)     = *(int4*)&h[0];    // 8 halves
        *(int4*)(g_Xh + e + 8) = *(int4*)&h[2];    // 8 halves
    } else if (b < PREP_WE0) {             // init_state
        int i = (b - PREP_ST0) * 256 + tid;
        if (b == PREP_ST0 && tid == 0) g_count = 0;
        g_C[i] = c0[i];
        g_Hhi[i] = __float2half_rn(h0[i]);
    } else if (b < PREP_WK0) {             // W_emb / W_out -> fp16
        int isout = (b >= PREP_WO0);
        const float* W = isout ? W_out : W_emb;
        __half* dst = isout ? g_Wout : g_Wemb;
        size_t q = (size_t)(b - (isout ? PREP_WO0 : PREP_WE0)) * 256 + tid;
        size_t e = q * 4;
        float4 v = *(const float4*)(W + e);
        H4 h;
        h.v[0] = __float2half_rn(v.x); h.v[1] = __float2half_rn(v.y);
        h.v[2] = __float2half_rn(v.z); h.v[3] = __float2half_rn(v.w);
        *(H4*)(dst + e) = h;
    } else {                               // W_k / W_r permuted -> fp16
        int isr = (b >= PREP_WR0);
        const float* W = isr ? W_r : W_k;
        __half* dst = isr ? g_Wr : g_Wk;
        size_t q = (size_t)(b - (isr ? PREP_WR0 : PREP_WK0)) * 256 + tid;
        int row = (int)(q >> 10);
        int qc = (int)(q & 1023);
        const float* src = W + (size_t)row * 4096 + qc;
        H4 h;
        h.v[0] = __float2half_rn(src[0]);
        h.v[1] = __float2half_rn(src[1024]);
        h.v[2] = __float2half_rn(src[2048]);
        h.v[3] = __float2half_rn(src[3072]);
        *(H4*)(dst + (size_t)row * 4096 + (size_t)qc * 4) = h;
    }
}

// ---------------- fp16 1-term wmma GEMM, 2-buffer cp.async pipeline (unchanged) ----------------
#define WG_BUF   18944
#define WG_BIAS  37888
#define WG_TOTAL 46080

__global__ __launch_bounds__(256) void wgemm(
    const __half* __restrict__ A, const __half* __restrict__ B,
    const float* __restrict__ bias, float* __restrict__ D,
    __half* __restrict__ Dh,
    int N, int mode)
{
    extern __shared__ char sm[];
    const uint32_t smb = (uint32_t)__cvta_generic_to_shared(sm);

    const int tid = threadIdx.x;
    const int n0 = blockIdx.x * 128, m0 = blockIdx.y * 128;
    const int wid = tid >> 5, lane = tid & 31;
    const int wm = wid & 3, wn = wid >> 2;

    float (*sbias)[128] = (float (*)[128])(sm + WG_BIAS);
    for (int i = tid; i < 2048; i += 256) {
        int col = i & 127;
        int p = n0 + col;
        float bv = (mode == 1) ? bias[(p & 3) * 1024 + (p >> 2)] : bias[p];
        sbias[i >> 7][col] = bv;
    }
    __syncthreads();

    wmma::fragment<wmma::accumulator, 16, 16, 16, float> acc[2][4];
#pragma unroll
    for (int i = 0; i < 2; i++)
#pragma unroll
        for (int j = 0; j < 4; j++)
            wmma::load_matrix_sync(acc[i][j], &sbias[0][wn * 64 + j * 16], 128, wmma::mem_row_major);
    __syncthreads();

    const int arow = tid >> 1, aseg = (tid & 1) * 16;
    const int brow = tid >> 3, bseg = (tid & 7) * 16;

    auto issue = [&](int c) {
        uint32_t base = smb + (uint32_t)(c & 1) * WG_BUF;
        int k0 = c * 32;
        uint32_t ad = base + (uint32_t)(arow * 40 + aseg) * 2;
        const __half* ap = A + (size_t)(m0 + arow) * 1024 + k0 + aseg;
        cp16(ad,      ap);
        cp16(ad + 16, ap + 8);
        uint32_t bd = base + 10240 + (uint32_t)(brow * 136 + bseg) * 2;
        const __half* bp = B + (size_t)(k0 + brow) * N + n0 + bseg;
        cp16(bd,      bp);
        cp16(bd + 16, bp + 8);
        cp_commit();
    };

    issue(0);
    for (int c = 0; c < 32; c++) {
        cp_wait<0>();
        __syncthreads();
        if (c + 1 < 32) issue(c + 1);

        char* bufp = sm + (c & 1) * WG_BUF;
        __half (*sA)[40]  = (__half (*)[40])(bufp);
        __half (*sB)[136] = (__half (*)[136])(bufp + 10240);

#pragma unroll
        for (int kk = 0; kk < 32; kk += 16) {
            wmma::fragment<wmma::matrix_a, 16, 16, 16, __half, wmma::row_major> ah[2];
            wmma::fragment<wmma::matrix_b, 16, 16, 16, __half, wmma::row_major> bh[4];
#pragma unroll
            for (int i = 0; i < 2; i++)
                wmma::load_matrix_sync(ah[i], &sA[wm * 32 + i * 16][kk], 40);
#pragma unroll
            for (int j = 0; j < 4; j++)
                wmma::load_matrix_sync(bh[j], &sB[kk][wn * 64 + j * 16], 136);
#pragma unroll
            for (int i = 0; i < 2; i++)
#pragma unroll
                for (int j = 0; j < 4; j++)
                    wmma::mma_sync(acc[i][j], ah[i], bh[j], acc[i][j]);
        }
    }

    if (mode == 0) {
        float (*stage)[16] = (float (*)[16])((float*)(sm + WG_BIAS) + wid * 256);
        __syncthreads();
#pragma unroll
        for (int i = 0; i < 2; i++)
#pragma unroll
            for (int j = 0; j < 4; j++) {
                for (int e = 0; e < acc[i][j].num_elements; e++)
                    acc[i][j].x[e] = fmaxf(acc[i][j].x[e], 0.f);
                wmma::store_matrix_sync(&stage[0][0], acc[i][j], 16, wmma::mem_row_major);
                __syncwarp();
                int r = lane & 15, c8 = (lane >> 4) * 8;
                size_t row = (size_t)(m0 + wm * 32 + i * 16 + r);
                size_t off = row * 1024 + (n0 + wn * 64 + j * 16 + c8);
                H4 h0v, h1v;
#pragma unroll
                for (int e = 0; e < 4; e++) h0v.v[e] = __float2half_rn(stage[r][c8 + e]);
#pragma unroll
                for (int e = 0; e < 4; e++) h1v.v[e] = __float2half_rn(stage[r][c8 + 4 + e]);
                *(H4*)(Dh + off)     = h0v;
                *(H4*)(Dh + off + 4) = h1v;
                __syncwarp();
            }
        return;
    }

#pragma unroll
    for (int i = 0; i < 2; i++)
#pragma unroll
        for (int j = 0; j < 4; j++) {
            int col = n0 + wn * 64 + j * 16;
            if (mode == 2) {
                int t = m0 >> 7;
                int b = wm * 32 + i * 16;
                float* p = D + (size_t)t * 1024 + (size_t)b * ((size_t)TN * 1024) + col;
                wmma::store_matrix_sync(p, acc[i][j], (unsigned)(TN * 1024), wmma::mem_row_major);
            } else {
                int row = m0 + wm * 32 + i * 16;
                wmma::store_matrix_sync(D + (size_t)row * N + col, acc[i][j], N, wmma::mem_row_major);
            }
        }
}

// ---------------- persistent recurrence: fp16 1-term, K-chunk 64, W in SMEM ----------------
// 128 CTAs x 512 thr. SMEM: WH[1024][40] 80K | A: 3 bufs x 18432 (hi[128][72]).
// 16 warps: (wm 0..3 = M32 tiles) x (wn 0..1 = N16) x (g 0..1 = K-half of 64-chunk).
// 2 independent acc chains per warp.
#define PS_WH 0
#define PS_A  81920
#define PS_ABUF 18432
#define PS_TOTAL (81920 + 3 * PS_ABUF)    // 137216

__global__ __launch_bounds__(512, 1) void lstm_persist6(const __half* __restrict__ W_g)
{
    extern __shared__ char sm[];
    const uint32_t smb = (uint32_t)__cvta_generic_to_shared(sm);
    const int tid = threadIdx.x, wid = tid >> 5;
    const int bx = blockIdx.x;
    const int n0g = bx * 32;
    const int g = wid >> 3, w8 = wid & 7;
    const int wm = w8 >> 1, wn = w8 & 1;

    for (int i = tid; i < 4096; i += 512) {
        int row = i >> 2, seg = (i & 3) * 8;
        cp16(smb + PS_WH + (uint32_t)(row * 40 + seg) * 2, W_g + (size_t)row * 4096 + n0g + seg);
    }
    cp_commit(); cp_wait<0>();
    __syncthreads();

    __half (*WH)[40] = (__half (*)[40])(sm + PS_WH);

    const int m = tid & 127, grp = tid >> 7;
    const int pc = grp * 8;
    float cv[2];
    {
        float2 c2 = *(const float2*)(g_C + (size_t)m * UN + bx * 8 + grp * 2);
        cv[0] = c2.x; cv[1] = c2.y;
    }
    const int arow = tid >> 2, aseg = (tid & 3) * 16;

    for (int t = 0; t < TN; t++) {
        const __half* __restrict__ Hhi = g_Hhi + (size_t)t * (BSZ * UN);

        float zkf[8];
        {
            const float* zk = g_ZK + ((size_t)t * BSZ + m) * 4096 + n0g + pc;
            float4 v0 = *(const float4*)(zk);
            float4 v1 = *(const float4*)(zk + 4);
            zkf[0] = v0.x; zkf[1] = v0.y; zkf[2] = v0.z; zkf[3] = v0.w;
            zkf[4] = v1.x; zkf[5] = v1.y; zkf[6] = v1.z; zkf[7] = v1.w;
        }

        auto issueA = [&](int chunk) {
            int buf = chunk % 3;
            uint32_t ad = smb + PS_A + buf * PS_ABUF + (uint32_t)(arow * 72 + aseg) * 2;
            const __half* src = Hhi + (size_t)arow * 1024 + chunk * 64 + aseg;
            cp16(ad,      src);
            cp16(ad + 16, src + 8);
            cp_commit();
        };

        wmma::fragment<wmma::accumulator, 16, 16, 16, float> a0[2];
        wmma::fill_fragment(a0[0], 0.f);
        wmma::fill_fragment(a0[1], 0.f);

        issueA(0); issueA(1);
        for (int c = 0; c < 16; c++) {
            if (c < 15) cp_wait<1>(); else cp_wait<0>();
            __syncthreads();
            if (c + 2 < 16) issueA(c + 2);

            int buf = c % 3;
            __half (*Ah)[72] = (__half (*)[72])(sm + PS_A + buf * PS_ABUF);

#pragma unroll
            for (int s = 0; s < 2; s++) {
                const int kkg = c * 64 + g * 32 + s * 16;
                const int ka  = g * 32 + s * 16;
                wmma::fragment<wmma::matrix_b, 16, 16, 16, __half, wmma::row_major> bh;
                wmma::fragment<wmma::matrix_a, 16, 16, 16, __half, wmma::row_major> ah0, ah1;
                wmma::load_matrix_sync(bh, &WH[kkg][wn * 16], 40);
                wmma::load_matrix_sync(ah0, &Ah[wm * 32][ka], 72);
                wmma::load_matrix_sync(ah1, &Ah[wm * 32 + 16][ka], 72);
                wmma::mma_sync(a0[0], ah0, bh, a0[0]);
                wmma::mma_sync(a0[1], ah1, bh, a0[1]);
            }
        }

        // partial z per K-group -> two smem buffers (overlay A buffers)
        __syncthreads();
        float (*zp)[36] = (float (*)[36])(sm + PS_A + g * 18432);
#pragma unroll
        for (int i = 0; i < 2; i++)
            wmma::store_matrix_sync(&zp[wm * 32 + i * 16][wn * 16], a0[i], 36, wmma::mem_row_major);
        __syncthreads();

        float (*z0)[36] = (float (*)[36])(sm + PS_A);
        float (*z1)[36] = (float (*)[36])(sm + PS_A + 18432);
        __half2 hh2;
#pragma unroll
        for (int e = 0; e < 2; e++) {
            float zi = z0[m][pc + e * 4 + 0] + z1[m][pc + e * 4 + 0] + zkf[e * 4 + 0];
            float zf = z0[m][pc + e * 4 + 1] + z1[m][pc + e * 4 + 1] + zkf[e * 4 + 1];
            float zg = z0[m][pc + e * 4 + 2] + z1[m][pc + e * 4 + 2] + zkf[e * 4 + 2];
            float zo = z0[m][pc + e * 4 + 3] + z1[m][pc + e * 4 + 3] + zkf[e * 4 + 3];
            float si = 1.f / (1.f + __expf(-zi));
            float sf = 1.f / (1.f + __expf(-zf));
            float so = 1.f / (1.f + __expf(-zo));
            float cn = sf * cv[e] + si * tanhf(zg);
            float hn = so * tanhf(cn);
            cv[e] = cn;
            __half h = __float2half_rn(hn);
            if (e == 0) hh2.x = h; else hh2.y = h;
        }
        size_t ho = (size_t)(t + 1) * (BSZ * UN) + (size_t)m * UN + bx * 8 + grp * 2;
        *(__half2*)(g_Hhi + ho) = hh2;

        __threadfence();
        __syncthreads();
        if (tid == 0) {
            atomicAdd(&g_count, 1);
            volatile int* gc = &g_count;
            int target = NCTA * (t + 1);
            while (*gc < target) __nanosleep(64);
        }
        __syncthreads();
    }
}

// ---------------- host ----------------
extern "C" void kernel_launch(void* const* d_in, const int* in_sizes, int n_in,
                              void* d_out, int out_size)
{
    const float* h0    = (const float*)d_in[0];
    const float* c0    = (const float*)d_in[1];
    const float* X     = (const float*)d_in[2];
    const float* W_emb = (const float*)d_in[3];
    const float* b_emb = (const float*)d_in[4];
    const float* W_k   = (const float*)d_in[5];
    const float* W_r   = (const float*)d_in[6];
    const float* b_r   = (const float*)d_in[7];
    const float* W_out = (const float*)d_in[8];
    const float* b_out = (const float*)d_in[9];
    (void)in_sizes; (void)n_in; (void)out_size;

    __half *pXh, *pEh, *pHhi, *pWemb, *pWout, *pWk, *pWr;
    float *pZK;
    cudaGetSymbolAddress((void**)&pXh, g_Xh);
    cudaGetSymbolAddress((void**)&pEh, g_Eh);
    cudaGetSymbolAddress((void**)&pHhi, g_Hhi);
    cudaGetSymbolAddress((void**)&pWemb, g_Wemb);
    cudaGetSymbolAddress((void**)&pWout, g_Wout);
    cudaGetSymbolAddress((void**)&pWk, g_Wk);
    cudaGetSymbolAddress((void**)&pWr, g_Wr);
    cudaGetSymbolAddress((void**)&pZK, g_ZK);

    cudaFuncSetAttribute(wgemm, cudaFuncAttributeMaxDynamicSharedMemorySize, WG_TOTAL);
    cudaFuncSetAttribute(lstm_persist6, cudaFuncAttributeMaxDynamicSharedMemorySize, PS_TOTAL);

    // 1. merged prep (also resets g_count each replay)
    prep_all<<<PREP_BLOCKS, 256>>>(X, h0, c0, W_emb, W_out, W_k, W_r);

    // 2. E = relu(X @ W_emb + b_emb) -> fp16
    {
        dim3 grid(1024 / 128, MROWS / 128);
        wgemm<<<grid, 256, WG_TOTAL>>>(pXh, pWemb, b_emb, nullptr, pEh, 1024, 0);
    }
    // 3. ZK = E @ W_k + b_r (fp32, permuted cols)
    {
        dim3 grid(4096 / 128, MROWS / 128);
        wgemm<<<grid, 256, WG_TOTAL>>>(pEh, pWk, b_r, pZK, nullptr, 4096, 1);
    }

    // 4. recurrence: persistent, fp16 1-term, chunk-64, W in SMEM
    lstm_persist6<<<NCTA, 512, PS_TOTAL>>>(pWr);

    // 5. OUT = H @ W_out + b_out, scattered to [b][t][:]
    {
        dim3 grid(1024 / 128, MROWS / 128);
        wgemm<<<grid, 256, WG_TOTAL>>>(pHhi + (size_t)BSZ * UN, pWout, b_out,
                                       (float*)d_out, nullptr, 1024, 2);
    }
}